// round 3
// baseline (speedup 1.0000x reference)
#include <cuda_runtime.h>
#include <math.h>

// ---------------------------------------------------------------------------
// Problem dims (fixed)
// ---------------------------------------------------------------------------
#define BN   32
#define CC   256
#define HID  512
#define SP   4096           // H*W
#define GRP  8
#define GC   64             // HID/GRP
#define BOT  64
#define NTOT (BN*SP)        // 131072
#define LRf  0.005f

// ---------------------------------------------------------------------------
// Static scratch (no allocations allowed)
// ---------------------------------------------------------------------------
__device__ float g_h1   [(size_t)BN*HID*SP];   // 268 MB
__device__ float g_act  [(size_t)BN*HID*SP];   // 268 MB (gelu output; reused for final pass)
__device__ float g_dy   [(size_t)BN*HID*SP];   // 268 MB (dy, then overwritten by dh1)
__device__ float g_z    [(size_t)BN*CC*SP];    // 134 MB
__device__ float g_rdiff[(size_t)BN*CC*SP];    // 134 MB ((rec-z)*inv)
__device__ float g_dz   [(size_t)BN*CC*SP];    // 134 MB
__device__ float g_pre  [(size_t)BN*BOT*SP];   // 33 MB
__device__ float g_dpre [(size_t)BN*BOT*SP];   // 33 MB
__device__ float g_mean [BN*GRP];
__device__ float g_rstd [BN*GRP];
__device__ float g_cm   [CC];
__device__ float g_cv   [CC];
__device__ float g_cnt  [1];
__device__ float g_Abk  [BN*HID];
__device__ float g_Bbk  [BN*HID];
__device__ float g_s1   [BN*GRP];
__device__ float g_s2   [BN*GRP];
__device__ float g_gnwf [HID];
__device__ float g_gnbf [HID];
__device__ float g_w1f  [HID*CC];
__device__ float g_w2f  [CC*HID];
__device__ float g_pw1  [(size_t)BN*HID*CC];   // per-b partial grad_w1
__device__ float g_pw2  [(size_t)BN*CC*HID];   // per-b partial grad_w2
__device__ float g_pool [BN*CC];
__device__ float g_gate [BN];

// ---------------------------------------------------------------------------
// Math helpers (exact GELU, matching jax approximate=False)
// ---------------------------------------------------------------------------
__device__ __forceinline__ float geluf(float x) {
    return 0.5f * x * (1.0f + erff(x * 0.70710678118654752f));
}
__device__ __forceinline__ float gelugradf(float x) {
    float cdf = 0.5f * (1.0f + erff(x * 0.70710678118654752f));
    float pdf = 0.3989422804014327f * expf(-0.5f * x * x);
    return cdf + x * pdf;
}

// ---------------------------------------------------------------------------
// Fused batched GEMM:  C[b] = A (MxK) * B[b] (KxSP), tiles 64x64x16, 4x4/thread
// PRE applies to B-element at load, EPI applies to accumulator at store.
// ---------------------------------------------------------------------------
enum { PRE_NONE = 0, PRE_MASK = 1, PRE_GELU = 2 };
enum { EPI_STORE = 0, EPI_ADDX = 1, EPI_RDIFF = 2, EPI_DPRE = 3,
       EPI_DZ = 4, EPI_DY = 5, EPI_FINAL = 6 };

struct EpiArgs {
    const float* x;
    const float* z;
    const float* rdiff;
    const float* pre;
    const float* cm;
    const float* cv;
    const float* cnt;
    const float* h1;
    const float* mean;
    const float* rstd;
    const float* gnw;
    const float* gnb;
    const float* gate;
    const float* rs;
};

template<int K, bool TA, int PRE, int EPI>
__global__ void __launch_bounds__(256)
gemm64(const float* __restrict__ A,
       const float* __restrict__ Bbase,
       float* __restrict__ Cbase,
       int M,
       const int* __restrict__ mask,
       EpiArgs ea)
{
    __shared__ float As[16][65];
    __shared__ float Bs[16][64];

    const int tid = threadIdx.x;
    const int tx = tid & 15, ty = tid >> 4;
    const int n0 = blockIdx.x * 64;
    const int m0 = blockIdx.y * 64;
    const int b  = blockIdx.z;

    const float* Bp = Bbase + (size_t)b * K * SP;
    float acc[4][4] = {};

    for (int kt = 0; kt < K; kt += 16) {
        if (!TA) {
            int ka = tid & 15, ma = tid >> 4;
            #pragma unroll
            for (int p = 0; p < 4; p++)
                As[ka][ma + 16 * p] = A[(size_t)(m0 + ma + 16 * p) * K + kt + ka];
        } else {
            int ma = tid & 63, ka = tid >> 6;
            #pragma unroll
            for (int p = 0; p < 4; p++)
                As[ka + 4 * p][ma] = A[(size_t)(kt + ka + 4 * p) * M + m0 + ma];
        }
        {
            int nb = tid & 63, kb = tid >> 6;
            #pragma unroll
            for (int p = 0; p < 4; p++) {
                float v = Bp[(size_t)(kt + kb + 4 * p) * SP + n0 + nb];
                if (PRE == PRE_MASK) v *= (float)mask[b * SP + n0 + nb];
                if (PRE == PRE_GELU) v = geluf(v);
                Bs[kb + 4 * p][nb] = v;
            }
        }
        __syncthreads();
        #pragma unroll
        for (int kk = 0; kk < 16; kk++) {
            float a[4], bb[4];
            #pragma unroll
            for (int i = 0; i < 4; i++) a[i] = As[kk][ty + 16 * i];
            #pragma unroll
            for (int j = 0; j < 4; j++) bb[j] = Bs[kk][tx + 16 * j];
            #pragma unroll
            for (int i = 0; i < 4; i++)
                #pragma unroll
                for (int j = 0; j < 4; j++)
                    acc[i][j] = fmaf(a[i], bb[j], acc[i][j]);
        }
        __syncthreads();
    }

    #pragma unroll
    for (int i = 0; i < 4; i++) {
        const int row = m0 + ty + 16 * i;
        #pragma unroll
        for (int j = 0; j < 4; j++) {
            const int col = n0 + tx + 16 * j;
            const size_t gi = (size_t)b * M * SP + (size_t)row * SP + col;
            float v = acc[i][j];
            float outv;
            if (EPI == EPI_STORE) {
                outv = v;
            } else if (EPI == EPI_ADDX) {
                outv = v + ea.x[gi];
            } else if (EPI == EPI_RDIFF) {
                float inv = 1.0f - (float)mask[b * SP + col];
                outv = (v - ea.z[gi]) * inv;
            } else if (EPI == EPI_DPRE) {
                float sc = 2.0f / (ea.cnt[0] * 256.0f + 1e-8f);
                outv = v * gelugradf(ea.pre[gi]) * sc;
            } else if (EPI == EPI_DZ) {
                float mk  = (float)mask[b * SP + col];
                float sc  = 2.0f / (ea.cnt[0] * 256.0f + 1e-8f);
                float zv  = ea.z[gi];
                float cmc = ea.cm[row];
                float cvs = ea.cv[row] * (1.0f / (1.0f + 1e-8f));
                float consist = 2.0f * cmc * (1.0f / (256.0f * 131072.0f))
                              + 4.0f * (cvs - 1.0f) * (zv - cmc)
                                * (1.0f / (256.0f * 131071.0f)) * (1.0f / (1.0f + 1e-8f));
                outv = mk * v - sc * ea.rdiff[gi] + 0.1f * consist;
            } else if (EPI == EPI_DY) {
                int gg = row >> 6;
                float mn = ea.mean[b * GRP + gg], rsd = ea.rstd[b * GRP + gg];
                float y = (ea.h1[gi] - mn) * rsd * ea.gnw[row] + ea.gnb[row];
                outv = v * gelugradf(y);
            } else { // EPI_FINAL
                outv = ea.x[gi] + ea.rs[0] * ea.gate[b] * v;
            }
            Cbase[gi] = outv;
        }
    }
}

// ---------------------------------------------------------------------------
// NT GEMM for weight grads: P[b][m][n] = sum_s A[b][m][s]*B[b][n][s]
// ---------------------------------------------------------------------------
__global__ void __launch_bounds__(256)
gemm_nt(const float* __restrict__ Abase, int Arows,
        const float* __restrict__ Bbase, int Brows,
        float* __restrict__ P, int M, int N)
{
    __shared__ float As[16][65];
    __shared__ float Bs[16][65];

    const int tid = threadIdx.x;
    const int tx = tid & 15, ty = tid >> 4;
    const int n0 = blockIdx.x * 64;
    const int m0 = blockIdx.y * 64;
    const int b  = blockIdx.z;

    const float* Ap = Abase + (size_t)b * Arows * SP;
    const float* Bp = Bbase + (size_t)b * Brows * SP;
    float acc[4][4] = {};

    for (int kt = 0; kt < SP; kt += 16) {
        int sa = tid & 15, ra = tid >> 4;
        #pragma unroll
        for (int p = 0; p < 4; p++) {
            As[sa][ra + 16 * p] = Ap[(size_t)(m0 + ra + 16 * p) * SP + kt + sa];
            Bs[sa][ra + 16 * p] = Bp[(size_t)(n0 + ra + 16 * p) * SP + kt + sa];
        }
        __syncthreads();
        #pragma unroll
        for (int kk = 0; kk < 16; kk++) {
            float a[4], bb[4];
            #pragma unroll
            for (int i = 0; i < 4; i++) a[i] = As[kk][ty + 16 * i];
            #pragma unroll
            for (int j = 0; j < 4; j++) bb[j] = Bs[kk][tx + 16 * j];
            #pragma unroll
            for (int i = 0; i < 4; i++)
                #pragma unroll
                for (int j = 0; j < 4; j++)
                    acc[i][j] = fmaf(a[i], bb[j], acc[i][j]);
        }
        __syncthreads();
    }
    #pragma unroll
    for (int i = 0; i < 4; i++)
        #pragma unroll
        for (int j = 0; j < 4; j++)
            P[(size_t)b * M * N + (size_t)(m0 + ty + 16 * i) * N + n0 + tx + 16 * j] = acc[i][j];
}

// ---------------------------------------------------------------------------
// Reductions / elementwise
// ---------------------------------------------------------------------------
__global__ void gn_stats_k(const float* __restrict__ h, float* __restrict__ mean,
                           float* __restrict__ rstd)
{
    const int bg = blockIdx.x;                 // b*8+g; group block is contiguous
    const float* p = h + (size_t)bg * (GC * SP);
    float s = 0.f, ss = 0.f;
    for (int i = threadIdx.x; i < GC * SP; i += 256) {
        float v = p[i]; s += v; ss += v * v;
    }
    __shared__ float sh1[256], sh2[256];
    sh1[threadIdx.x] = s; sh2[threadIdx.x] = ss;
    __syncthreads();
    for (int o = 128; o > 0; o >>= 1) {
        if (threadIdx.x < o) { sh1[threadIdx.x] += sh1[threadIdx.x + o];
                               sh2[threadIdx.x] += sh2[threadIdx.x + o]; }
        __syncthreads();
    }
    if (threadIdx.x == 0) {
        float m = sh1[0] * (1.0f / (GC * SP));
        float var = sh2[0] * (1.0f / (GC * SP)) - m * m;
        mean[bg] = m;
        rstd[bg] = rsqrtf(var + 1e-5f);
    }
}

__global__ void gn_gelu_k(const float* __restrict__ h, const float* __restrict__ mean,
                          const float* __restrict__ rstd, const float* __restrict__ gnw,
                          const float* __restrict__ gnb, float* __restrict__ out)
{
    size_t i4 = (size_t)blockIdx.x * 256 + threadIdx.x;    // 16777216 float4s
    size_t base = i4 * 4;
    int k  = (int)((base >> 12) & 511);
    int bg = (int)(base >> 18);
    float m = mean[bg], r = rstd[bg], w = gnw[k], bb = gnb[k];
    float4 v = ((const float4*)h)[i4];
    float4 o;
    o.x = geluf((v.x - m) * r * w + bb);
    o.y = geluf((v.y - m) * r * w + bb);
    o.z = geluf((v.z - m) * r * w + bb);
    o.w = geluf((v.w - m) * r * w + bb);
    ((float4*)out)[i4] = o;
}

__global__ void zstats_k(const float* __restrict__ z, float* __restrict__ cm,
                         float* __restrict__ cv)
{
    const int c = blockIdx.x;
    float s = 0.f, ss = 0.f;
    for (int b = 0; b < BN; b++) {
        const float* p = z + (size_t)b * CC * SP + (size_t)c * SP;
        for (int i = threadIdx.x; i < SP; i += 256) { float v = p[i]; s += v; ss += v * v; }
    }
    __shared__ float sh1[256], sh2[256];
    sh1[threadIdx.x] = s; sh2[threadIdx.x] = ss;
    __syncthreads();
    for (int o = 128; o > 0; o >>= 1) {
        if (threadIdx.x < o) { sh1[threadIdx.x] += sh1[threadIdx.x + o];
                               sh2[threadIdx.x] += sh2[threadIdx.x + o]; }
        __syncthreads();
    }
    if (threadIdx.x == 0) {
        float m = sh1[0] * (1.0f / NTOT);
        cm[c] = m;
        cv[c] = (sh2[0] - (float)NTOT * m * m) * (1.0f / (NTOT - 1));
    }
}

__global__ void mask_count_k(const int* __restrict__ mask, float* __restrict__ cnt)
{
    int s = 0;
    for (int i = threadIdx.x; i < NTOT; i += 256) s += 1 - mask[i];
    __shared__ int sh[256];
    sh[threadIdx.x] = s;
    __syncthreads();
    for (int o = 128; o > 0; o >>= 1) {
        if (threadIdx.x < o) sh[threadIdx.x] += sh[threadIdx.x + o];
        __syncthreads();
    }
    if (threadIdx.x == 0) cnt[0] = (float)sh[0];
}

__global__ void bkpart_k(const float* __restrict__ dy, const float* __restrict__ h1,
                         const float* __restrict__ mean, const float* __restrict__ rstd,
                         float* __restrict__ Abk, float* __restrict__ Bbk)
{
    const int bk = blockIdx.x;            // b*512+k
    const int b = bk >> 9, k = bk & 511, g = k >> 6;
    const float* pd = dy + (size_t)bk * SP;
    const float* ph = h1 + (size_t)bk * SP;
    const float m = mean[b * GRP + g], r = rstd[b * GRP + g];
    float s1 = 0.f, s2 = 0.f;
    for (int i = threadIdx.x; i < SP; i += 128) {
        float d = pd[i];
        float xh = (ph[i] - m) * r;
        s1 += d; s2 += d * xh;
    }
    __shared__ float sh1[128], sh2[128];
    sh1[threadIdx.x] = s1; sh2[threadIdx.x] = s2;
    __syncthreads();
    for (int o = 64; o > 0; o >>= 1) {
        if (threadIdx.x < o) { sh1[threadIdx.x] += sh1[threadIdx.x + o];
                               sh2[threadIdx.x] += sh2[threadIdx.x + o]; }
        __syncthreads();
    }
    if (threadIdx.x == 0) { Abk[bk] = sh1[0]; Bbk[bk] = sh2[0]; }
}

__global__ void gn_update_k(const float* __restrict__ Abk, const float* __restrict__ Bbk,
                            const float* __restrict__ gnw, const float* __restrict__ gnb,
                            float* __restrict__ gnwf, float* __restrict__ gnbf)
{
    const int k = threadIdx.x;            // 512
    float ga = 0.f, gw = 0.f;
    for (int b = 0; b < BN; b++) { ga += Abk[b * HID + k]; gw += Bbk[b * HID + k]; }
    gnbf[k] = gnb[k] - LRf * ga;
    gnwf[k] = gnw[k] - LRf * gw;
}

__global__ void s12_k(const float* __restrict__ Abk, const float* __restrict__ Bbk,
                      const float* __restrict__ gnw, float* __restrict__ s1,
                      float* __restrict__ s2)
{
    const int bg = threadIdx.x;           // 256 = b*8+g
    const int b = bg >> 3, g = bg & 7;
    float a = 0.f, c = 0.f;
    for (int l = 0; l < GC; l++) {
        int k = g * GC + l;
        float w = gnw[k];
        a += w * Abk[b * HID + k];
        c += w * Bbk[b * HID + k];
    }
    s1[bg] = a; s2[bg] = c;
}

__global__ void dh1_k(float* __restrict__ dy, const float* __restrict__ h1,
                      const float* __restrict__ mean, const float* __restrict__ rstd,
                      const float* __restrict__ gnw, const float* __restrict__ s1,
                      const float* __restrict__ s2)
{
    size_t i4 = (size_t)blockIdx.x * 256 + threadIdx.x;
    size_t base = i4 * 4;
    int k  = (int)((base >> 12) & 511);
    int bg = (int)(base >> 18);
    float m = mean[bg], r = rstd[bg], w = gnw[k];
    const float invM = 1.0f / (GC * SP);
    float a = s1[bg] * invM, c = s2[bg] * invM;
    float4 d = ((const float4*)dy)[i4];
    float4 h = ((const float4*)h1)[i4];
    d.x = r * (w * d.x - a - (h.x - m) * r * c);
    d.y = r * (w * d.y - a - (h.y - m) * r * c);
    d.z = r * (w * d.z - a - (h.z - m) * r * c);
    d.w = r * (w * d.w - a - (h.w - m) * r * c);
    ((float4*)dy)[i4] = d;
}

__global__ void reduce_update_k(const float* __restrict__ P, const float* __restrict__ w,
                                float* __restrict__ wf, int MN)
{
    int i = blockIdx.x * 256 + threadIdx.x;
    if (i < MN) {
        float s = 0.f;
        for (int b = 0; b < BN; b++) s += P[(size_t)b * MN + i];
        wf[i] = w[i] - LRf * s;
    }
}

__global__ void pooled_k(const float* __restrict__ x, float* __restrict__ pooled)
{
    const int bc = blockIdx.x;            // 8192
    const float* p = x + (size_t)bc * SP;
    float s = 0.f;
    for (int i = threadIdx.x; i < SP; i += 128) s += p[i];
    __shared__ float sh[128];
    sh[threadIdx.x] = s;
    __syncthreads();
    for (int o = 64; o > 0; o >>= 1) {
        if (threadIdx.x < o) sh[threadIdx.x] += sh[threadIdx.x + o];
        __syncthreads();
    }
    if (threadIdx.x == 0) pooled[bc] = sh[0] * (1.0f / SP);
}

__global__ void gate_k(const float* __restrict__ pooled, const float* __restrict__ gw1,
                       const float* __restrict__ gb1, const float* __restrict__ gw2,
                       const float* __restrict__ gb2, float* __restrict__ gate)
{
    const int b = blockIdx.x;
    const int j = threadIdx.x;            // 64
    float acc = gb1[j];
    for (int c = 0; c < CC; c++) acc += pooled[b * CC + c] * gw1[j * CC + c];
    __shared__ float sh[64];
    sh[j] = geluf(acc) * gw2[j];
    __syncthreads();
    for (int o = 32; o > 0; o >>= 1) {
        if (j < o) sh[j] += sh[j + o];
        __syncthreads();
    }
    if (j == 0) gate[b] = 1.0f / (1.0f + expf(-(sh[0] + gb2[0])));
}

// ---------------------------------------------------------------------------
// Launch
// ---------------------------------------------------------------------------
extern "C" void kernel_launch(void* const* d_in, const int* in_sizes, int n_in,
                              void* d_out, int out_size)
{
    const float* x    = (const float*)d_in[0];
    const int*   mask = (const int*)  d_in[1];
    const float* w1   = (const float*)d_in[2];
    const float* gnw  = (const float*)d_in[3];
    const float* gnb  = (const float*)d_in[4];
    const float* w2   = (const float*)d_in[5];
    const float* rc1  = (const float*)d_in[6];
    const float* rc2  = (const float*)d_in[7];
    const float* gw1  = (const float*)d_in[8];
    const float* gb1  = (const float*)d_in[9];
    const float* gw2  = (const float*)d_in[10];
    const float* gb2  = (const float*)d_in[11];
    const float* rs   = (const float*)d_in[12];
    float* out = (float*)d_out;
    (void)in_sizes; (void)n_in; (void)out_size;

    float *h1, *act, *dyb, *z, *rdiff, *dz, *pre, *dpre;
    float *meanb, *rstdb, *cm, *cv, *cnt, *Abk, *Bbk, *s1, *s2;
    float *gnwf, *gnbf, *w1f, *w2f, *pw1, *pw2, *pooled, *gate;
    cudaGetSymbolAddress((void**)&h1,    g_h1);
    cudaGetSymbolAddress((void**)&act,   g_act);
    cudaGetSymbolAddress((void**)&dyb,   g_dy);
    cudaGetSymbolAddress((void**)&z,     g_z);
    cudaGetSymbolAddress((void**)&rdiff, g_rdiff);
    cudaGetSymbolAddress((void**)&dz,    g_dz);
    cudaGetSymbolAddress((void**)&pre,   g_pre);
    cudaGetSymbolAddress((void**)&dpre,  g_dpre);
    cudaGetSymbolAddress((void**)&meanb, g_mean);
    cudaGetSymbolAddress((void**)&rstdb, g_rstd);
    cudaGetSymbolAddress((void**)&cm,    g_cm);
    cudaGetSymbolAddress((void**)&cv,    g_cv);
    cudaGetSymbolAddress((void**)&cnt,   g_cnt);
    cudaGetSymbolAddress((void**)&Abk,   g_Abk);
    cudaGetSymbolAddress((void**)&Bbk,   g_Bbk);
    cudaGetSymbolAddress((void**)&s1,    g_s1);
    cudaGetSymbolAddress((void**)&s2,    g_s2);
    cudaGetSymbolAddress((void**)&gnwf,  g_gnwf);
    cudaGetSymbolAddress((void**)&gnbf,  g_gnbf);
    cudaGetSymbolAddress((void**)&w1f,   g_w1f);
    cudaGetSymbolAddress((void**)&w2f,   g_w2f);
    cudaGetSymbolAddress((void**)&pw1,   g_pw1);
    cudaGetSymbolAddress((void**)&pw2,   g_pw2);
    cudaGetSymbolAddress((void**)&pooled,g_pool);
    cudaGetSymbolAddress((void**)&gate,  g_gate);

    // --- gate path (independent of everything but x) ---
    pooled_k<<<BN * CC, 128>>>(x, pooled);
    gate_k<<<BN, 64>>>(pooled, gw1, gb1, gw2, gb2, gate);
    mask_count_k<<<1, 256>>>(mask, cnt);

    // --- forward modifier at original params ---
    { EpiArgs ea = {};
      gemm64<256, false, PRE_NONE, EPI_STORE><<<dim3(64, 8, BN), 256>>>(w1, x, h1, HID, mask, ea); }
    gn_stats_k<<<BN * GRP, 256>>>(h1, meanb, rstdb);
    gn_gelu_k<<<65536, 256>>>(h1, meanb, rstdb, gnw, gnb, act);
    { EpiArgs ea = {}; ea.x = x;
      gemm64<512, false, PRE_NONE, EPI_ADDX><<<dim3(64, 4, BN), 256>>>(w2, act, z, CC, mask, ea); }

    // --- surprise loss forward + dz ---
    zstats_k<<<CC, 256>>>(z, cm, cv);
    { EpiArgs ea = {};
      gemm64<256, false, PRE_MASK, EPI_STORE><<<dim3(64, 1, BN), 256>>>(rc1, z, pre, BOT, mask, ea); }
    { EpiArgs ea = {}; ea.z = z;
      gemm64<64, false, PRE_GELU, EPI_RDIFF><<<dim3(64, 4, BN), 256>>>(rc2, pre, rdiff, CC, mask, ea); }
    { EpiArgs ea = {}; ea.pre = pre; ea.cnt = cnt;
      gemm64<256, true, PRE_NONE, EPI_DPRE><<<dim3(64, 1, BN), 256>>>(rc2, rdiff, dpre, BOT, mask, ea); }
    { EpiArgs ea = {}; ea.rdiff = rdiff; ea.z = z; ea.cm = cm; ea.cv = cv; ea.cnt = cnt;
      gemm64<64, true, PRE_NONE, EPI_DZ><<<dim3(64, 4, BN), 256>>>(rc1, dpre, dz, CC, mask, ea); }

    // --- backward through modifier ---
    { EpiArgs ea = {}; ea.h1 = h1; ea.mean = meanb; ea.rstd = rstdb; ea.gnw = gnw; ea.gnb = gnb;
      gemm64<256, true, PRE_NONE, EPI_DY><<<dim3(64, 8, BN), 256>>>(w2, dz, dyb, HID, mask, ea); }
    bkpart_k<<<BN * HID, 128>>>(dyb, h1, meanb, rstdb, Abk, Bbk);
    gn_update_k<<<1, HID>>>(Abk, Bbk, gnw, gnb, gnwf, gnbf);
    s12_k<<<1, BN * GRP>>>(Abk, Bbk, gnw, s1, s2);
    dh1_k<<<65536, 256>>>(dyb, h1, meanb, rstdb, gnw, s1, s2);

    gemm_nt<<<dim3(4, 8, BN), 256>>>(dyb, HID, x, CC, pw1, HID, CC);
    reduce_update_k<<<512, 256>>>(pw1, w1, w1f, HID * CC);
    gemm_nt<<<dim3(8, 4, BN), 256>>>(dz, CC, act, HID, pw2, CC, HID);
    reduce_update_k<<<512, 256>>>(pw2, w2, w2f, CC * HID);

    // --- final modifier at fast weights + residual/gate epilogue ---
    { EpiArgs ea = {};
      gemm64<256, false, PRE_NONE, EPI_STORE><<<dim3(64, 8, BN), 256>>>(w1f, x, h1, HID, mask, ea); }
    gn_stats_k<<<BN * GRP, 256>>>(h1, meanb, rstdb);
    gn_gelu_k<<<65536, 256>>>(h1, meanb, rstdb, gnwf, gnbf, act);
    { EpiArgs ea = {}; ea.x = x; ea.gate = gate; ea.rs = rs;
      gemm64<512, false, PRE_NONE, EPI_FINAL><<<dim3(64, 4, BN), 256>>>(w2f, act, out, CC, mask, ea); }
}

// round 4
// speedup vs baseline: 1.2668x; 1.2668x over previous
#include <cuda_runtime.h>
#include <math.h>

// ---------------------------------------------------------------------------
// Problem dims (fixed)
// ---------------------------------------------------------------------------
#define BN   32
#define CC   256
#define HID  512
#define SP   4096           // H*W
#define GRP  8
#define GC   64             // HID/GRP
#define BOT  64
#define NTOT (BN*SP)        // 131072
#define LRf  0.005f

// ---------------------------------------------------------------------------
// Static scratch (no allocations allowed)
// ---------------------------------------------------------------------------
__device__ float g_h1   [(size_t)BN*HID*SP];
__device__ float g_act  [(size_t)BN*HID*SP];
__device__ float g_dy   [(size_t)BN*HID*SP];
__device__ float g_z    [(size_t)BN*CC*SP];
__device__ float g_rdiff[(size_t)BN*CC*SP];
__device__ float g_dz   [(size_t)BN*CC*SP];
__device__ float g_pre  [(size_t)BN*BOT*SP];
__device__ float g_dpre [(size_t)BN*BOT*SP];
__device__ float g_mean [BN*GRP];
__device__ float g_rstd [BN*GRP];
__device__ float g_cm   [CC];
__device__ float g_cv   [CC];
__device__ float g_cnt  [1];
__device__ float g_Abk  [BN*HID];
__device__ float g_Bbk  [BN*HID];
__device__ float g_s1   [BN*GRP];
__device__ float g_s2   [BN*GRP];
__device__ float g_gnwf [HID];
__device__ float g_gnbf [HID];
__device__ float g_w1f  [HID*CC];
__device__ float g_w2f  [CC*HID];
__device__ float g_pw1  [(size_t)BN*HID*CC];
__device__ float g_pw2  [(size_t)BN*CC*HID];
__device__ float g_pool [BN*CC];
__device__ float g_gate [BN];

// ---------------------------------------------------------------------------
// Math helpers (exact GELU, matching jax approximate=False)
// ---------------------------------------------------------------------------
__device__ __forceinline__ float geluf(float x) {
    return 0.5f * x * (1.0f + erff(x * 0.70710678118654752f));
}
__device__ __forceinline__ float gelugradf(float x) {
    float cdf = 0.5f * (1.0f + erff(x * 0.70710678118654752f));
    float pdf = 0.3989422804014327f * expf(-0.5f * x * x);
    return cdf + x * pdf;
}

// f32x2 packed helpers (FFMA2 — 2 fp32 FMAs per instruction, PTX-only)
__device__ __forceinline__ unsigned long long pk2(float v) {
    unsigned long long r;
    asm("mov.b64 %0, {%1, %1};" : "=l"(r) : "f"(v));
    return r;
}
__device__ __forceinline__ void fma2(unsigned long long& c, unsigned long long a,
                                     unsigned long long b) {
    asm("fma.rn.f32x2 %0, %1, %2, %0;" : "+l"(c) : "l"(a), "l"(b));
}
__device__ __forceinline__ float2 upk(unsigned long long p) {
    float2 r;
    asm("mov.b64 {%0, %1}, %2;" : "=f"(r.x), "=f"(r.y) : "l"(p));
    return r;
}

// ---------------------------------------------------------------------------
// Fused batched GEMM:  C[b] = A (MxK) * B[b] (KxSP)
// Tile MT x 128 x 16, per-thread (MT/16) x 8 via f32x2 FMA.
// ---------------------------------------------------------------------------
enum { PRE_NONE = 0, PRE_MASK = 1, PRE_GELU = 2 };
enum { EPI_STORE = 0, EPI_ADDX = 1, EPI_RDIFF = 2, EPI_DPRE = 3,
       EPI_DZ = 4, EPI_DY = 5, EPI_FINAL = 6 };

struct EpiArgs {
    const float* x;
    const float* z;
    const float* rdiff;
    const float* pre;
    const float* cm;
    const float* cv;
    const float* cnt;
    const float* h1;
    const float* mean;
    const float* rstd;
    const float* gnw;
    const float* gnb;
    const float* gate;
    const float* rs;
};

template<int MT, int K, bool TA, int PRE, int EPI>
__global__ void __launch_bounds__(256, 2)
gemmX(const float* __restrict__ A,
      const float* __restrict__ Bbase,
      float* __restrict__ Cbase,
      int M,
      const int* __restrict__ mask,
      EpiArgs ea)
{
    constexpr int RT = MT / 16;                 // rows per thread (8 or 4)
    __shared__ __align__(16) float As[16][MT];
    __shared__ __align__(16) float Bs[16][128];

    const int tid = threadIdx.x;
    const int tx = tid & 15;                    // col group: cols tx*8 .. +7
    const int ty = tid >> 4;                    // row group: rows ty*RT .. +RT-1
    const int n0 = blockIdx.x * 128;
    const int m0 = blockIdx.y * MT;
    const int b  = blockIdx.z;

    const float* Bp = Bbase + (size_t)b * K * SP;

    unsigned long long acc[RT][4];
    #pragma unroll
    for (int i = 0; i < RT; i++)
        #pragma unroll
        for (int j = 0; j < 4; j++) acc[i][j] = 0ull;

    for (int kt = 0; kt < K; kt += 16) {
        // ---- load A tile (transposed into As[k][m]) ----
        if (!TA) {
            if (MT == 128) {
                int row = tid & 127, ks = (tid >> 7) * 8;
                const float* ap = A + (size_t)(m0 + row) * K + kt + ks;
                float4 v0 = *(const float4*)ap;
                float4 v1 = *(const float4*)(ap + 4);
                As[ks + 0][row] = v0.x; As[ks + 1][row] = v0.y;
                As[ks + 2][row] = v0.z; As[ks + 3][row] = v0.w;
                As[ks + 4][row] = v1.x; As[ks + 5][row] = v1.y;
                As[ks + 6][row] = v1.z; As[ks + 7][row] = v1.w;
            } else {
                int row = tid & 63, ks = (tid >> 6) * 4;
                float4 v0 = *(const float4*)(A + (size_t)(m0 + row) * K + kt + ks);
                As[ks + 0][row] = v0.x; As[ks + 1][row] = v0.y;
                As[ks + 2][row] = v0.z; As[ks + 3][row] = v0.w;
            }
        } else {
            if (MT == 128) {
                int m = (tid & 31) * 4, k0 = tid >> 5;
                #pragma unroll
                for (int it = 0; it < 2; it++) {
                    int k = k0 + 8 * it;
                    *(float4*)&As[k][m] = *(const float4*)(A + (size_t)(kt + k) * M + m0 + m);
                }
            } else {
                int m = (tid & 15) * 4, k = tid >> 4;
                *(float4*)&As[k][m] = *(const float4*)(A + (size_t)(kt + k) * M + m0 + m);
            }
        }
        // ---- load B tile ----
        {
            int n = (tid & 31) * 4, k0 = tid >> 5;
            #pragma unroll
            for (int it = 0; it < 2; it++) {
                int k = k0 + 8 * it;
                float4 v = *(const float4*)(Bp + (size_t)(kt + k) * SP + n0 + n);
                if (PRE == PRE_MASK) {
                    int4 mk = *(const int4*)(mask + b * SP + n0 + n);
                    v.x *= (float)mk.x; v.y *= (float)mk.y;
                    v.z *= (float)mk.z; v.w *= (float)mk.w;
                }
                if (PRE == PRE_GELU) {
                    v.x = geluf(v.x); v.y = geluf(v.y);
                    v.z = geluf(v.z); v.w = geluf(v.w);
                }
                *(float4*)&Bs[k][n] = v;
            }
        }
        __syncthreads();
        #pragma unroll
        for (int kk = 0; kk < 16; kk++) {
            ulonglong2 b01 = *(const ulonglong2*)&Bs[kk][tx * 8];
            ulonglong2 b23 = *(const ulonglong2*)&Bs[kk][tx * 8 + 4];
            unsigned long long bp2[4] = { b01.x, b01.y, b23.x, b23.y };
            float av[RT];
            if (MT == 128) {
                float4 a0 = *(const float4*)&As[kk][ty * 8];
                float4 a1 = *(const float4*)&As[kk][ty * 8 + 4];
                av[0] = a0.x; av[1] = a0.y; av[2] = a0.z; av[3] = a0.w;
                av[4] = a1.x; av[5] = a1.y; av[6] = a1.z; av[7] = a1.w;
            } else {
                float4 a0 = *(const float4*)&As[kk][ty * 4];
                av[0] = a0.x; av[1] = a0.y; av[2] = a0.z; av[3] = a0.w;
            }
            #pragma unroll
            for (int i = 0; i < RT; i++) {
                unsigned long long ap2 = pk2(av[i]);
                #pragma unroll
                for (int j = 0; j < 4; j++) fma2(acc[i][j], ap2, bp2[j]);
            }
        }
        __syncthreads();
    }

    // ---- epilogue: 8 cols per row, vectorized stores ----
    #pragma unroll
    for (int i = 0; i < RT; i++) {
        const int row = m0 + ty * RT + i;
        float ov[8];
        #pragma unroll
        for (int j = 0; j < 4; j++) {
            float2 p = upk(acc[i][j]);
            ov[2 * j] = p.x; ov[2 * j + 1] = p.y;
        }
        const int colb = n0 + tx * 8;
        const size_t gib = (size_t)b * M * SP + (size_t)row * SP + colb;
        #pragma unroll
        for (int j = 0; j < 8; j++) {
            const int col = colb + j;
            const size_t gi = gib + j;
            float v = ov[j];
            float outv;
            if (EPI == EPI_STORE) {
                outv = v;
            } else if (EPI == EPI_ADDX) {
                outv = v + ea.x[gi];
            } else if (EPI == EPI_RDIFF) {
                float inv = 1.0f - (float)mask[b * SP + col];
                outv = (v - ea.z[gi]) * inv;
            } else if (EPI == EPI_DPRE) {
                float sc = 2.0f / (ea.cnt[0] * 256.0f + 1e-8f);
                outv = v * gelugradf(ea.pre[gi]) * sc;
            } else if (EPI == EPI_DZ) {
                float mk  = (float)mask[b * SP + col];
                float sc  = 2.0f / (ea.cnt[0] * 256.0f + 1e-8f);
                float zv  = ea.z[gi];
                float cmc = ea.cm[row];
                float cvs = ea.cv[row] * (1.0f / (1.0f + 1e-8f));
                float consist = 2.0f * cmc * (1.0f / (256.0f * 131072.0f))
                              + 4.0f * (cvs - 1.0f) * (zv - cmc)
                                * (1.0f / (256.0f * 131071.0f)) * (1.0f / (1.0f + 1e-8f));
                outv = mk * v - sc * ea.rdiff[gi] + 0.1f * consist;
            } else if (EPI == EPI_DY) {
                int gg = row >> 6;
                float mn = ea.mean[b * GRP + gg], rsd = ea.rstd[b * GRP + gg];
                float y = (ea.h1[gi] - mn) * rsd * ea.gnw[row] + ea.gnb[row];
                outv = v * gelugradf(y);
            } else { // EPI_FINAL
                outv = ea.x[gi] + ea.rs[0] * ea.gate[b] * v;
            }
            ov[j] = outv;
        }
        *(float4*)(Cbase + gib)     = make_float4(ov[0], ov[1], ov[2], ov[3]);
        *(float4*)(Cbase + gib + 4) = make_float4(ov[4], ov[5], ov[6], ov[7]);
    }
}

// ---------------------------------------------------------------------------
// NT GEMM for weight grads: P[b][m][n] = sum_s A[b][m][s]*B[b][n][s]
// Tile 128x128x16, f32x2 inner loop (both operands transpose-on-load).
// ---------------------------------------------------------------------------
__global__ void __launch_bounds__(256, 2)
gemm_ntX(const float* __restrict__ Abase, int Arows,
         const float* __restrict__ Bbase, int Brows,
         float* __restrict__ P, int M, int N)
{
    __shared__ __align__(16) float As[16][128];
    __shared__ __align__(16) float Bs[16][128];

    const int tid = threadIdx.x;
    const int tx = tid & 15, ty = tid >> 4;
    const int n0 = blockIdx.x * 128;
    const int m0 = blockIdx.y * 128;
    const int b  = blockIdx.z;

    const float* Ap = Abase + (size_t)b * Arows * SP;
    const float* Bp = Bbase + (size_t)b * Brows * SP;

    unsigned long long acc[8][4];
    #pragma unroll
    for (int i = 0; i < 8; i++)
        #pragma unroll
        for (int j = 0; j < 4; j++) acc[i][j] = 0ull;

    const int lrow = tid & 127, lks = (tid >> 7) * 8;

    for (int kt = 0; kt < SP; kt += 16) {
        {
            const float* ap = Ap + (size_t)(m0 + lrow) * SP + kt + lks;
            float4 v0 = *(const float4*)ap;
            float4 v1 = *(const float4*)(ap + 4);
            As[lks + 0][lrow] = v0.x; As[lks + 1][lrow] = v0.y;
            As[lks + 2][lrow] = v0.z; As[lks + 3][lrow] = v0.w;
            As[lks + 4][lrow] = v1.x; As[lks + 5][lrow] = v1.y;
            As[lks + 6][lrow] = v1.z; As[lks + 7][lrow] = v1.w;
            const float* bp = Bp + (size_t)(n0 + lrow) * SP + kt + lks;
            float4 w0 = *(const float4*)bp;
            float4 w1 = *(const float4*)(bp + 4);
            Bs[lks + 0][lrow] = w0.x; Bs[lks + 1][lrow] = w0.y;
            Bs[lks + 2][lrow] = w0.z; Bs[lks + 3][lrow] = w0.w;
            Bs[lks + 4][lrow] = w1.x; Bs[lks + 5][lrow] = w1.y;
            Bs[lks + 6][lrow] = w1.z; Bs[lks + 7][lrow] = w1.w;
        }
        __syncthreads();
        #pragma unroll
        for (int kk = 0; kk < 16; kk++) {
            ulonglong2 b01 = *(const ulonglong2*)&Bs[kk][tx * 8];
            ulonglong2 b23 = *(const ulonglong2*)&Bs[kk][tx * 8 + 4];
            unsigned long long bp2[4] = { b01.x, b01.y, b23.x, b23.y };
            float4 a0 = *(const float4*)&As[kk][ty * 8];
            float4 a1 = *(const float4*)&As[kk][ty * 8 + 4];
            float av[8] = { a0.x, a0.y, a0.z, a0.w, a1.x, a1.y, a1.z, a1.w };
            #pragma unroll
            for (int i = 0; i < 8; i++) {
                unsigned long long ap2 = pk2(av[i]);
                #pragma unroll
                for (int j = 0; j < 4; j++) fma2(acc[i][j], ap2, bp2[j]);
            }
        }
        __syncthreads();
    }
    #pragma unroll
    for (int i = 0; i < 8; i++) {
        const int row = m0 + ty * 8 + i;
        float ov[8];
        #pragma unroll
        for (int j = 0; j < 4; j++) {
            float2 p = upk(acc[i][j]);
            ov[2 * j] = p.x; ov[2 * j + 1] = p.y;
        }
        float* pp = P + (size_t)b * M * N + (size_t)row * N + n0 + tx * 8;
        *(float4*)pp       = make_float4(ov[0], ov[1], ov[2], ov[3]);
        *(float4*)(pp + 4) = make_float4(ov[4], ov[5], ov[6], ov[7]);
    }
}

// ---------------------------------------------------------------------------
// Reductions / elementwise
// ---------------------------------------------------------------------------
__global__ void gn_stats_k(const float* __restrict__ h, float* __restrict__ mean,
                           float* __restrict__ rstd)
{
    const int bg = blockIdx.x;
    const float* p = h + (size_t)bg * (GC * SP);
    float s = 0.f, ss = 0.f;
    for (int i = threadIdx.x; i < GC * SP; i += 256) {
        float v = p[i]; s += v; ss += v * v;
    }
    __shared__ float sh1[256], sh2[256];
    sh1[threadIdx.x] = s; sh2[threadIdx.x] = ss;
    __syncthreads();
    for (int o = 128; o > 0; o >>= 1) {
        if (threadIdx.x < o) { sh1[threadIdx.x] += sh1[threadIdx.x + o];
                               sh2[threadIdx.x] += sh2[threadIdx.x + o]; }
        __syncthreads();
    }
    if (threadIdx.x == 0) {
        float m = sh1[0] * (1.0f / (GC * SP));
        float var = sh2[0] * (1.0f / (GC * SP)) - m * m;
        mean[bg] = m;
        rstd[bg] = rsqrtf(var + 1e-5f);
    }
}

__global__ void gn_gelu_k(const float* __restrict__ h, const float* __restrict__ mean,
                          const float* __restrict__ rstd, const float* __restrict__ gnw,
                          const float* __restrict__ gnb, float* __restrict__ out)
{
    size_t i4 = (size_t)blockIdx.x * 256 + threadIdx.x;
    size_t base = i4 * 4;
    int k  = (int)((base >> 12) & 511);
    int bg = (int)(base >> 18);
    float m = mean[bg], r = rstd[bg], w = gnw[k], bb = gnb[k];
    float4 v = ((const float4*)h)[i4];
    float4 o;
    o.x = geluf((v.x - m) * r * w + bb);
    o.y = geluf((v.y - m) * r * w + bb);
    o.z = geluf((v.z - m) * r * w + bb);
    o.w = geluf((v.w - m) * r * w + bb);
    ((float4*)out)[i4] = o;
}

__global__ void zstats_k(const float* __restrict__ z, float* __restrict__ cm,
                         float* __restrict__ cv)
{
    const int c = blockIdx.x;
    float s = 0.f, ss = 0.f;
    for (int b = 0; b < BN; b++) {
        const float* p = z + (size_t)b * CC * SP + (size_t)c * SP;
        for (int i = threadIdx.x; i < SP; i += 256) { float v = p[i]; s += v; ss += v * v; }
    }
    __shared__ float sh1[256], sh2[256];
    sh1[threadIdx.x] = s; sh2[threadIdx.x] = ss;
    __syncthreads();
    for (int o = 128; o > 0; o >>= 1) {
        if (threadIdx.x < o) { sh1[threadIdx.x] += sh1[threadIdx.x + o];
                               sh2[threadIdx.x] += sh2[threadIdx.x + o]; }
        __syncthreads();
    }
    if (threadIdx.x == 0) {
        float m = sh1[0] * (1.0f / NTOT);
        cm[c] = m;
        cv[c] = (sh2[0] - (float)NTOT * m * m) * (1.0f / (NTOT - 1));
    }
}

__global__ void mask_count_k(const int* __restrict__ mask, float* __restrict__ cnt)
{
    int s = 0;
    for (int i = threadIdx.x; i < NTOT; i += 256) s += 1 - mask[i];
    __shared__ int sh[256];
    sh[threadIdx.x] = s;
    __syncthreads();
    for (int o = 128; o > 0; o >>= 1) {
        if (threadIdx.x < o) sh[threadIdx.x] += sh[threadIdx.x + o];
        __syncthreads();
    }
    if (threadIdx.x == 0) cnt[0] = (float)sh[0];
}

__global__ void bkpart_k(const float* __restrict__ dy, const float* __restrict__ h1,
                         const float* __restrict__ mean, const float* __restrict__ rstd,
                         float* __restrict__ Abk, float* __restrict__ Bbk)
{
    const int bk = blockIdx.x;
    const int b = bk >> 9, k = bk & 511, g = k >> 6;
    const float* pd = dy + (size_t)bk * SP;
    const float* ph = h1 + (size_t)bk * SP;
    const float m = mean[b * GRP + g], r = rstd[b * GRP + g];
    float s1 = 0.f, s2 = 0.f;
    for (int i = threadIdx.x; i < SP; i += 128) {
        float d = pd[i];
        float xh = (ph[i] - m) * r;
        s1 += d; s2 += d * xh;
    }
    __shared__ float sh1[128], sh2[128];
    sh1[threadIdx.x] = s1; sh2[threadIdx.x] = s2;
    __syncthreads();
    for (int o = 64; o > 0; o >>= 1) {
        if (threadIdx.x < o) { sh1[threadIdx.x] += sh1[threadIdx.x + o];
                               sh2[threadIdx.x] += sh2[threadIdx.x + o]; }
        __syncthreads();
    }
    if (threadIdx.x == 0) { Abk[bk] = sh1[0]; Bbk[bk] = sh2[0]; }
}

__global__ void gn_update_k(const float* __restrict__ Abk, const float* __restrict__ Bbk,
                            const float* __restrict__ gnw, const float* __restrict__ gnb,
                            float* __restrict__ gnwf, float* __restrict__ gnbf)
{
    const int k = threadIdx.x;
    float ga = 0.f, gw = 0.f;
    for (int b = 0; b < BN; b++) { ga += Abk[b * HID + k]; gw += Bbk[b * HID + k]; }
    gnbf[k] = gnb[k] - LRf * ga;
    gnwf[k] = gnw[k] - LRf * gw;
}

__global__ void s12_k(const float* __restrict__ Abk, const float* __restrict__ Bbk,
                      const float* __restrict__ gnw, float* __restrict__ s1,
                      float* __restrict__ s2)
{
    const int bg = threadIdx.x;
    const int b = bg >> 3, g = bg & 7;
    float a = 0.f, c = 0.f;
    for (int l = 0; l < GC; l++) {
        int k = g * GC + l;
        float w = gnw[k];
        a += w * Abk[b * HID + k];
        c += w * Bbk[b * HID + k];
    }
    s1[bg] = a; s2[bg] = c;
}

__global__ void dh1_k(float* __restrict__ dy, const float* __restrict__ h1,
                      const float* __restrict__ mean, const float* __restrict__ rstd,
                      const float* __restrict__ gnw, const float* __restrict__ s1,
                      const float* __restrict__ s2)
{
    size_t i4 = (size_t)blockIdx.x * 256 + threadIdx.x;
    size_t base = i4 * 4;
    int k  = (int)((base >> 12) & 511);
    int bg = (int)(base >> 18);
    float m = mean[bg], r = rstd[bg], w = gnw[k];
    const float invM = 1.0f / (GC * SP);
    float a = s1[bg] * invM, c = s2[bg] * invM;
    float4 d = ((const float4*)dy)[i4];
    float4 h = ((const float4*)h1)[i4];
    d.x = r * (w * d.x - a - (h.x - m) * r * c);
    d.y = r * (w * d.y - a - (h.y - m) * r * c);
    d.z = r * (w * d.z - a - (h.z - m) * r * c);
    d.w = r * (w * d.w - a - (h.w - m) * r * c);
    ((float4*)dy)[i4] = d;
}

__global__ void reduce_update_k(const float* __restrict__ P, const float* __restrict__ w,
                                float* __restrict__ wf, int MN)
{
    int i = blockIdx.x * 256 + threadIdx.x;
    if (i < MN) {
        float s = 0.f;
        for (int b = 0; b < BN; b++) s += P[(size_t)b * MN + i];
        wf[i] = w[i] - LRf * s;
    }
}

__global__ void pooled_k(const float* __restrict__ x, float* __restrict__ pooled)
{
    const int bc = blockIdx.x;
    const float* p = x + (size_t)bc * SP;
    float s = 0.f;
    for (int i = threadIdx.x; i < SP; i += 128) s += p[i];
    __shared__ float sh[128];
    sh[threadIdx.x] = s;
    __syncthreads();
    for (int o = 64; o > 0; o >>= 1) {
        if (threadIdx.x < o) sh[threadIdx.x] += sh[threadIdx.x + o];
        __syncthreads();
    }
    if (threadIdx.x == 0) pooled[bc] = sh[0] * (1.0f / SP);
}

__global__ void gate_k(const float* __restrict__ pooled, const float* __restrict__ gw1,
                       const float* __restrict__ gb1, const float* __restrict__ gw2,
                       const float* __restrict__ gb2, float* __restrict__ gate)
{
    const int b = blockIdx.x;
    const int j = threadIdx.x;
    float acc = gb1[j];
    for (int c = 0; c < CC; c++) acc += pooled[b * CC + c] * gw1[j * CC + c];
    __shared__ float sh[64];
    sh[j] = geluf(acc) * gw2[j];
    __syncthreads();
    for (int o = 32; o > 0; o >>= 1) {
        if (j < o) sh[j] += sh[j + o];
        __syncthreads();
    }
    if (j == 0) gate[b] = 1.0f / (1.0f + expf(-(sh[0] + gb2[0])));
}

// ---------------------------------------------------------------------------
// Launch
// ---------------------------------------------------------------------------
extern "C" void kernel_launch(void* const* d_in, const int* in_sizes, int n_in,
                              void* d_out, int out_size)
{
    const float* x    = (const float*)d_in[0];
    const int*   mask = (const int*)  d_in[1];
    const float* w1   = (const float*)d_in[2];
    const float* gnw  = (const float*)d_in[3];
    const float* gnb  = (const float*)d_in[4];
    const float* w2   = (const float*)d_in[5];
    const float* rc1  = (const float*)d_in[6];
    const float* rc2  = (const float*)d_in[7];
    const float* gw1  = (const float*)d_in[8];
    const float* gb1  = (const float*)d_in[9];
    const float* gw2  = (const float*)d_in[10];
    const float* gb2  = (const float*)d_in[11];
    const float* rs   = (const float*)d_in[12];
    float* out = (float*)d_out;
    (void)in_sizes; (void)n_in; (void)out_size;

    float *h1, *act, *dyb, *z, *rdiff, *dz, *pre, *dpre;
    float *meanb, *rstdb, *cm, *cv, *cnt, *Abk, *Bbk, *s1, *s2;
    float *gnwf, *gnbf, *w1f, *w2f, *pw1, *pw2, *pooled, *gate;
    cudaGetSymbolAddress((void**)&h1,    g_h1);
    cudaGetSymbolAddress((void**)&act,   g_act);
    cudaGetSymbolAddress((void**)&dyb,   g_dy);
    cudaGetSymbolAddress((void**)&z,     g_z);
    cudaGetSymbolAddress((void**)&rdiff, g_rdiff);
    cudaGetSymbolAddress((void**)&dz,    g_dz);
    cudaGetSymbolAddress((void**)&pre,   g_pre);
    cudaGetSymbolAddress((void**)&dpre,  g_dpre);
    cudaGetSymbolAddress((void**)&meanb, g_mean);
    cudaGetSymbolAddress((void**)&rstdb, g_rstd);
    cudaGetSymbolAddress((void**)&cm,    g_cm);
    cudaGetSymbolAddress((void**)&cv,    g_cv);
    cudaGetSymbolAddress((void**)&cnt,   g_cnt);
    cudaGetSymbolAddress((void**)&Abk,   g_Abk);
    cudaGetSymbolAddress((void**)&Bbk,   g_Bbk);
    cudaGetSymbolAddress((void**)&s1,    g_s1);
    cudaGetSymbolAddress((void**)&s2,    g_s2);
    cudaGetSymbolAddress((void**)&gnwf,  g_gnwf);
    cudaGetSymbolAddress((void**)&gnbf,  g_gnbf);
    cudaGetSymbolAddress((void**)&w1f,   g_w1f);
    cudaGetSymbolAddress((void**)&w2f,   g_w2f);
    cudaGetSymbolAddress((void**)&pw1,   g_pw1);
    cudaGetSymbolAddress((void**)&pw2,   g_pw2);
    cudaGetSymbolAddress((void**)&pooled,g_pool);
    cudaGetSymbolAddress((void**)&gate,  g_gate);

    // --- gate path (independent of everything but x) ---
    pooled_k<<<BN * CC, 128>>>(x, pooled);
    gate_k<<<BN, 64>>>(pooled, gw1, gb1, gw2, gb2, gate);
    mask_count_k<<<1, 256>>>(mask, cnt);

    // --- forward modifier at original params ---
    { EpiArgs ea = {};
      gemmX<128, 256, false, PRE_NONE, EPI_STORE><<<dim3(32, 4, BN), 256>>>(w1, x, h1, HID, mask, ea); }
    gn_stats_k<<<BN * GRP, 256>>>(h1, meanb, rstdb);
    gn_gelu_k<<<65536, 256>>>(h1, meanb, rstdb, gnw, gnb, act);
    { EpiArgs ea = {}; ea.x = x;
      gemmX<128, 512, false, PRE_NONE, EPI_ADDX><<<dim3(32, 2, BN), 256>>>(w2, act, z, CC, mask, ea); }

    // --- surprise loss forward + dz ---
    zstats_k<<<CC, 256>>>(z, cm, cv);
    { EpiArgs ea = {};
      gemmX<64, 256, false, PRE_MASK, EPI_STORE><<<dim3(32, 1, BN), 256>>>(rc1, z, pre, BOT, mask, ea); }
    { EpiArgs ea = {}; ea.z = z;
      gemmX<128, 64, false, PRE_GELU, EPI_RDIFF><<<dim3(32, 2, BN), 256>>>(rc2, pre, rdiff, CC, mask, ea); }
    { EpiArgs ea = {}; ea.pre = pre; ea.cnt = cnt;
      gemmX<64, 256, true, PRE_NONE, EPI_DPRE><<<dim3(32, 1, BN), 256>>>(rc2, rdiff, dpre, BOT, mask, ea); }
    { EpiArgs ea = {}; ea.rdiff = rdiff; ea.z = z; ea.cm = cm; ea.cv = cv; ea.cnt = cnt;
      gemmX<128, 64, true, PRE_NONE, EPI_DZ><<<dim3(32, 2, BN), 256>>>(rc1, dpre, dz, CC, mask, ea); }

    // --- backward through modifier ---
    { EpiArgs ea = {}; ea.h1 = h1; ea.mean = meanb; ea.rstd = rstdb; ea.gnw = gnw; ea.gnb = gnb;
      gemmX<128, 256, true, PRE_NONE, EPI_DY><<<dim3(32, 4, BN), 256>>>(w2, dz, dyb, HID, mask, ea); }
    bkpart_k<<<BN * HID, 128>>>(dyb, h1, meanb, rstdb, Abk, Bbk);
    gn_update_k<<<1, HID>>>(Abk, Bbk, gnw, gnb, gnwf, gnbf);
    s12_k<<<1, BN * GRP>>>(Abk, Bbk, gnw, s1, s2);
    dh1_k<<<65536, 256>>>(dyb, h1, meanb, rstdb, gnw, s1, s2);

    gemm_ntX<<<dim3(2, 4, BN), 256>>>(dyb, HID, x, CC, pw1, HID, CC);
    reduce_update_k<<<512, 256>>>(pw1, w1, w1f, HID * CC);
    gemm_ntX<<<dim3(4, 2, BN), 256>>>(dz, CC, act, HID, pw2, CC, HID);
    reduce_update_k<<<512, 256>>>(pw2, w2, w2f, CC * HID);

    // --- final modifier at fast weights + residual/gate epilogue ---
    { EpiArgs ea = {};
      gemmX<128, 256, false, PRE_NONE, EPI_STORE><<<dim3(32, 4, BN), 256>>>(w1f, x, h1, HID, mask, ea); }
    gn_stats_k<<<BN * GRP, 256>>>(h1, meanb, rstdb);
    gn_gelu_k<<<65536, 256>>>(h1, meanb, rstdb, gnwf, gnbf, act);
    { EpiArgs ea = {}; ea.x = x; ea.gate = gate; ea.rs = rs;
      gemmX<128, 512, false, PRE_NONE, EPI_FINAL><<<dim3(32, 2, BN), 256>>>(w2f, act, out, CC, mask, ea); }
}

// round 6
// speedup vs baseline: 1.2675x; 1.0005x over previous
#include <cuda_runtime.h>
#include <math.h>

// ---------------------------------------------------------------------------
// Problem dims (fixed)
// ---------------------------------------------------------------------------
#define BN   32
#define CC   256
#define HID  512
#define SP   4096           // H*W
#define GRP  8
#define GC   64             // HID/GRP
#define BOT  64
#define NTOT (BN*SP)        // 131072
#define LRf  0.005f

// ---------------------------------------------------------------------------
// Static scratch (no allocations allowed)
// ---------------------------------------------------------------------------
__device__ float g_h1   [(size_t)BN*HID*SP];
__device__ float g_act  [(size_t)BN*HID*SP];
__device__ float g_dy   [(size_t)BN*HID*SP];
__device__ float g_z    [(size_t)BN*CC*SP];
__device__ float g_rdiff[(size_t)BN*CC*SP];
__device__ float g_dz   [(size_t)BN*CC*SP];
__device__ float g_pre  [(size_t)BN*BOT*SP];
__device__ float g_dpre [(size_t)BN*BOT*SP];
__device__ float g_mean [BN*GRP];
__device__ float g_rstd [BN*GRP];
__device__ float g_cm   [CC];
__device__ float g_cv   [CC];
__device__ float g_cnt  [1];
__device__ float g_Abk  [BN*HID];
__device__ float g_Bbk  [BN*HID];
__device__ float g_s1   [BN*GRP];
__device__ float g_s2   [BN*GRP];
__device__ float g_gnwf [HID];
__device__ float g_gnbf [HID];
__device__ float g_w1f  [HID*CC];
__device__ float g_w2f  [CC*HID];
__device__ float g_pw1  [(size_t)BN*HID*CC];
__device__ float g_pw2  [(size_t)BN*CC*HID];
__device__ float g_pool [BN*CC];
__device__ float g_gate [BN];

// ---------------------------------------------------------------------------
// Math helpers (exact GELU, matching jax approximate=False)
// ---------------------------------------------------------------------------
__device__ __forceinline__ float geluf(float x) {
    return 0.5f * x * (1.0f + erff(x * 0.70710678118654752f));
}
__device__ __forceinline__ float gelugradf(float x) {
    float cdf = 0.5f * (1.0f + erff(x * 0.70710678118654752f));
    float pdf = 0.3989422804014327f * expf(-0.5f * x * x);
    return cdf + x * pdf;
}

// f32x2 packed helpers (FFMA2 — 2 fp32 FMAs per instruction, PTX-only)
__device__ __forceinline__ unsigned long long pk2(float v) {
    unsigned long long r;
    asm("mov.b64 %0, {%1, %1};" : "=l"(r) : "f"(v));
    return r;
}
__device__ __forceinline__ void fma2(unsigned long long& c, unsigned long long a,
                                     unsigned long long b) {
    asm("fma.rn.f32x2 %0, %1, %2, %0;" : "+l"(c) : "l"(a), "l"(b));
}
__device__ __forceinline__ float2 upk(unsigned long long p) {
    float2 r;
    asm("mov.b64 {%0, %1}, %2;" : "=f"(r.x), "=f"(r.y) : "l"(p));
    return r;
}

// ---------------------------------------------------------------------------
// Fused batched GEMM:  C[b] = A (MxK) * B[b] (KxSP)
// Tile MT x 128 x 16, per-thread (MT/16) x 8 via f32x2 FMA.
// ---------------------------------------------------------------------------
enum { PRE_NONE = 0, PRE_MASK = 1, PRE_GELU = 2 };
enum { EPI_STORE = 0, EPI_ADDX = 1, EPI_RDIFF = 2, EPI_DPRE = 3,
       EPI_DZ = 4, EPI_DY = 5, EPI_FINAL = 6 };

struct EpiArgs {
    const float* x;
    const float* z;
    const float* rdiff;
    const float* pre;
    const float* cm;
    const float* cv;
    const float* cnt;
    const float* h1;
    const float* mean;
    const float* rstd;
    const float* gnw;
    const float* gnb;
    const float* gate;
    const float* rs;
};

template<int MT, int K, bool TA, int PRE, int EPI>
__global__ void __launch_bounds__(256, 2)
gemmX(const float* __restrict__ A,
      const float* __restrict__ Bbase,
      float* __restrict__ Cbase,
      int M,
      const int* __restrict__ mask,
      EpiArgs ea)
{
    constexpr int RT = MT / 16;                 // rows per thread (8 or 4)
    __shared__ __align__(16) float As[16][MT];
    __shared__ __align__(16) float Bs[16][128];

    const int tid = threadIdx.x;
    const int tx = tid & 15;                    // col group: cols tx*8 .. +7
    const int ty = tid >> 4;                    // row group: rows ty*RT .. +RT-1
    const int n0 = blockIdx.x * 128;
    const int m0 = blockIdx.y * MT;
    const int b  = blockIdx.z;

    const float* Bp = Bbase + (size_t)b * K * SP;

    unsigned long long acc[RT][4];
    #pragma unroll
    for (int i = 0; i < RT; i++)
        #pragma unroll
        for (int j = 0; j < 4; j++) acc[i][j] = 0ull;

    for (int kt = 0; kt < K; kt += 16) {
        // ---- load A tile (transposed into As[k][m]) ----
        if (!TA) {
            if (MT == 128) {
                int row = tid & 127, ks = (tid >> 7) * 8;
                const float* ap = A + (size_t)(m0 + row) * K + kt + ks;
                float4 v0 = *(const float4*)ap;
                float4 v1 = *(const float4*)(ap + 4);
                As[ks + 0][row] = v0.x; As[ks + 1][row] = v0.y;
                As[ks + 2][row] = v0.z; As[ks + 3][row] = v0.w;
                As[ks + 4][row] = v1.x; As[ks + 5][row] = v1.y;
                As[ks + 6][row] = v1.z; As[ks + 7][row] = v1.w;
            } else {
                int row = tid & 63, ks = (tid >> 6) * 4;
                float4 v0 = *(const float4*)(A + (size_t)(m0 + row) * K + kt + ks);
                As[ks + 0][row] = v0.x; As[ks + 1][row] = v0.y;
                As[ks + 2][row] = v0.z; As[ks + 3][row] = v0.w;
            }
        } else {
            if (MT == 128) {
                int m = (tid & 31) * 4, k0 = tid >> 5;
                #pragma unroll
                for (int it = 0; it < 2; it++) {
                    int k = k0 + 8 * it;
                    *(float4*)&As[k][m] = *(const float4*)(A + (size_t)(kt + k) * M + m0 + m);
                }
            } else {
                int m = (tid & 15) * 4, k = tid >> 4;
                *(float4*)&As[k][m] = *(const float4*)(A + (size_t)(kt + k) * M + m0 + m);
            }
        }
        // ---- load B tile ----
        {
            int n = (tid & 31) * 4, k0 = tid >> 5;
            #pragma unroll
            for (int it = 0; it < 2; it++) {
                int k = k0 + 8 * it;
                float4 v = *(const float4*)(Bp + (size_t)(kt + k) * SP + n0 + n);
                if (PRE == PRE_MASK) {
                    int4 mk = *(const int4*)(mask + b * SP + n0 + n);
                    v.x *= (float)mk.x; v.y *= (float)mk.y;
                    v.z *= (float)mk.z; v.w *= (float)mk.w;
                }
                if (PRE == PRE_GELU) {
                    v.x = geluf(v.x); v.y = geluf(v.y);
                    v.z = geluf(v.z); v.w = geluf(v.w);
                }
                *(float4*)&Bs[k][n] = v;
            }
        }
        __syncthreads();
        #pragma unroll
        for (int kk = 0; kk < 16; kk++) {
            ulonglong2 b01 = *(const ulonglong2*)&Bs[kk][tx * 8];
            ulonglong2 b23 = *(const ulonglong2*)&Bs[kk][tx * 8 + 4];
            unsigned long long bp2[4] = { b01.x, b01.y, b23.x, b23.y };
            float av[RT];
            if (MT == 128) {
                float4 a0 = *(const float4*)&As[kk][ty * 8];
                float4 a1 = *(const float4*)&As[kk][ty * 8 + 4];
                av[0] = a0.x; av[1] = a0.y; av[2] = a0.z; av[3] = a0.w;
                av[4] = a1.x; av[5] = a1.y; av[6] = a1.z; av[7] = a1.w;
            } else {
                float4 a0 = *(const float4*)&As[kk][ty * 4];
                av[0] = a0.x; av[1] = a0.y; av[2] = a0.z; av[3] = a0.w;
            }
            #pragma unroll
            for (int i = 0; i < RT; i++) {
                unsigned long long ap2 = pk2(av[i]);
                #pragma unroll
                for (int j = 0; j < 4; j++) fma2(acc[i][j], ap2, bp2[j]);
            }
        }
        __syncthreads();
    }

    // ---- epilogue: 8 cols per row, vectorized stores ----
    #pragma unroll
    for (int i = 0; i < RT; i++) {
        const int row = m0 + ty * RT + i;
        float ov[8];
        #pragma unroll
        for (int j = 0; j < 4; j++) {
            float2 p = upk(acc[i][j]);
            ov[2 * j] = p.x; ov[2 * j + 1] = p.y;
        }
        const int colb = n0 + tx * 8;
        const size_t gib = (size_t)b * M * SP + (size_t)row * SP + colb;
        #pragma unroll
        for (int j = 0; j < 8; j++) {
            const int col = colb + j;
            const size_t gi = gib + j;
            float v = ov[j];
            float outv;
            if (EPI == EPI_STORE) {
                outv = v;
            } else if (EPI == EPI_ADDX) {
                outv = v + ea.x[gi];
            } else if (EPI == EPI_RDIFF) {
                float inv = 1.0f - (float)mask[b * SP + col];
                outv = (v - ea.z[gi]) * inv;
            } else if (EPI == EPI_DPRE) {
                float sc = 2.0f / (ea.cnt[0] * 256.0f + 1e-8f);
                outv = v * gelugradf(ea.pre[gi]) * sc;
            } else if (EPI == EPI_DZ) {
                float mk  = (float)mask[b * SP + col];
                float sc  = 2.0f / (ea.cnt[0] * 256.0f + 1e-8f);
                float zv  = ea.z[gi];
                float cmc = ea.cm[row];
                float cvs = ea.cv[row] * (1.0f / (1.0f + 1e-8f));
                float consist = 2.0f * cmc * (1.0f / (256.0f * 131072.0f))
                              + 4.0f * (cvs - 1.0f) * (zv - cmc)
                                * (1.0f / (256.0f * 131071.0f)) * (1.0f / (1.0f + 1e-8f));
                outv = mk * v - sc * ea.rdiff[gi] + 0.1f * consist;
            } else if (EPI == EPI_DY) {
                int gg = row >> 6;
                float mn = ea.mean[b * GRP + gg], rsd = ea.rstd[b * GRP + gg];
                float y = (ea.h1[gi] - mn) * rsd * ea.gnw[row] + ea.gnb[row];
                outv = v * gelugradf(y);
            } else { // EPI_FINAL
                outv = ea.x[gi] + ea.rs[0] * ea.gate[b] * v;
            }
            ov[j] = outv;
        }
        *(float4*)(Cbase + gib)     = make_float4(ov[0], ov[1], ov[2], ov[3]);
        *(float4*)(Cbase + gib + 4) = make_float4(ov[4], ov[5], ov[6], ov[7]);
    }
}

// ---------------------------------------------------------------------------
// NT GEMM for weight grads: P[b][m][n] = sum_s A[b][m][s]*B[b][n][s]
// Tile 128x128x16, f32x2 inner loop (both operands transpose-on-load).
// ---------------------------------------------------------------------------
__global__ void __launch_bounds__(256, 2)
gemm_ntX(const float* __restrict__ Abase, int Arows,
         const float* __restrict__ Bbase, int Brows,
         float* __restrict__ P, int M, int N)
{
    __shared__ __align__(16) float As[16][128];
    __shared__ __align__(16) float Bs[16][128];

    const int tid = threadIdx.x;
    const int tx = tid & 15, ty = tid >> 4;
    const int n0 = blockIdx.x * 128;
    const int m0 = blockIdx.y * 128;
    const int b  = blockIdx.z;

    const float* Ap = Abase + (size_t)b * Arows * SP;
    const float* Bp = Bbase + (size_t)b * Brows * SP;

    unsigned long long acc[8][4];
    #pragma unroll
    for (int i = 0; i < 8; i++)
        #pragma unroll
        for (int j = 0; j < 4; j++) acc[i][j] = 0ull;

    const int lrow = tid & 127, lks = (tid >> 7) * 8;

    for (int kt = 0; kt < SP; kt += 16) {
        {
            const float* ap = Ap + (size_t)(m0 + lrow) * SP + kt + lks;
            float4 v0 = *(const float4*)ap;
            float4 v1 = *(const float4*)(ap + 4);
            As[lks + 0][lrow] = v0.x; As[lks + 1][lrow] = v0.y;
            As[lks + 2][lrow] = v0.z; As[lks + 3][lrow] = v0.w;
            As[lks + 4][lrow] = v1.x; As[lks + 5][lrow] = v1.y;
            As[lks + 6][lrow] = v1.z; As[lks + 7][lrow] = v1.w;
            const float* bp = Bp + (size_t)(n0 + lrow) * SP + kt + lks;
            float4 w0 = *(const float4*)bp;
            float4 w1 = *(const float4*)(bp + 4);
            Bs[lks + 0][lrow] = w0.x; Bs[lks + 1][lrow] = w0.y;
            Bs[lks + 2][lrow] = w0.z; Bs[lks + 3][lrow] = w0.w;
            Bs[lks + 4][lrow] = w1.x; Bs[lks + 5][lrow] = w1.y;
            Bs[lks + 6][lrow] = w1.z; Bs[lks + 7][lrow] = w1.w;
        }
        __syncthreads();
        #pragma unroll
        for (int kk = 0; kk < 16; kk++) {
            ulonglong2 b01 = *(const ulonglong2*)&Bs[kk][tx * 8];
            ulonglong2 b23 = *(const ulonglong2*)&Bs[kk][tx * 8 + 4];
            unsigned long long bp2[4] = { b01.x, b01.y, b23.x, b23.y };
            float4 a0 = *(const float4*)&As[kk][ty * 8];
            float4 a1 = *(const float4*)&As[kk][ty * 8 + 4];
            float av[8] = { a0.x, a0.y, a0.z, a0.w, a1.x, a1.y, a1.z, a1.w };
            #pragma unroll
            for (int i = 0; i < 8; i++) {
                unsigned long long ap2 = pk2(av[i]);
                #pragma unroll
                for (int j = 0; j < 4; j++) fma2(acc[i][j], ap2, bp2[j]);
            }
        }
        __syncthreads();
    }
    #pragma unroll
    for (int i = 0; i < 8; i++) {
        const int row = m0 + ty * 8 + i;
        float ov[8];
        #pragma unroll
        for (int j = 0; j < 4; j++) {
            float2 p = upk(acc[i][j]);
            ov[2 * j] = p.x; ov[2 * j + 1] = p.y;
        }
        float* pp = P + (size_t)b * M * N + (size_t)row * N + n0 + tx * 8;
        *(float4*)pp       = make_float4(ov[0], ov[1], ov[2], ov[3]);
        *(float4*)(pp + 4) = make_float4(ov[4], ov[5], ov[6], ov[7]);
    }
}

// ---------------------------------------------------------------------------
// Reductions / elementwise
// ---------------------------------------------------------------------------
__global__ void gn_stats_k(const float* __restrict__ h, float* __restrict__ mean,
                           float* __restrict__ rstd)
{
    const int bg = blockIdx.x;
    const float* p = h + (size_t)bg * (GC * SP);
    float s = 0.f, ss = 0.f;
    for (int i = threadIdx.x; i < GC * SP; i += 256) {
        float v = p[i]; s += v; ss += v * v;
    }
    __shared__ float sh1[256], sh2[256];
    sh1[threadIdx.x] = s; sh2[threadIdx.x] = ss;
    __syncthreads();
    for (int o = 128; o > 0; o >>= 1) {
        if (threadIdx.x < o) { sh1[threadIdx.x] += sh1[threadIdx.x + o];
                               sh2[threadIdx.x] += sh2[threadIdx.x + o]; }
        __syncthreads();
    }
    if (threadIdx.x == 0) {
        float m = sh1[0] * (1.0f / (GC * SP));
        float var = sh2[0] * (1.0f / (GC * SP)) - m * m;
        mean[bg] = m;
        rstd[bg] = rsqrtf(var + 1e-5f);
    }
}

__global__ void gn_gelu_k(const float* __restrict__ h, const float* __restrict__ mean,
                          const float* __restrict__ rstd, const float* __restrict__ gnw,
                          const float* __restrict__ gnb, float* __restrict__ out)
{
    size_t i4 = (size_t)blockIdx.x * 256 + threadIdx.x;
    size_t base = i4 * 4;
    int k  = (int)((base >> 12) & 511);
    int bg = (int)(base >> 18);
    float m = mean[bg], r = rstd[bg], w = gnw[k], bb = gnb[k];
    float4 v = ((const float4*)h)[i4];
    float4 o;
    o.x = geluf((v.x - m) * r * w + bb);
    o.y = geluf((v.y - m) * r * w + bb);
    o.z = geluf((v.z - m) * r * w + bb);
    o.w = geluf((v.w - m) * r * w + bb);
    ((float4*)out)[i4] = o;
}

__global__ void zstats_k(const float* __restrict__ z, float* __restrict__ cm,
                         float* __restrict__ cv)
{
    const int c = blockIdx.x;
    float s = 0.f, ss = 0.f;
    for (int b = 0; b < BN; b++) {
        const float* p = z + (size_t)b * CC * SP + (size_t)c * SP;
        for (int i = threadIdx.x; i < SP; i += 256) { float v = p[i]; s += v; ss += v * v; }
    }
    __shared__ float sh1[256], sh2[256];
    sh1[threadIdx.x] = s; sh2[threadIdx.x] = ss;
    __syncthreads();
    for (int o = 128; o > 0; o >>= 1) {
        if (threadIdx.x < o) { sh1[threadIdx.x] += sh1[threadIdx.x + o];
                               sh2[threadIdx.x] += sh2[threadIdx.x + o]; }
        __syncthreads();
    }
    if (threadIdx.x == 0) {
        float m = sh1[0] * (1.0f / NTOT);
        cm[c] = m;
        cv[c] = (sh2[0] - (float)NTOT * m * m) * (1.0f / (NTOT - 1));
    }
}

__global__ void mask_count_k(const int* __restrict__ mask, float* __restrict__ cnt)
{
    int s = 0;
    for (int i = threadIdx.x; i < NTOT; i += 256) s += 1 - mask[i];
    __shared__ int sh[256];
    sh[threadIdx.x] = s;
    __syncthreads();
    for (int o = 128; o > 0; o >>= 1) {
        if (threadIdx.x < o) sh[threadIdx.x] += sh[threadIdx.x + o];
        __syncthreads();
    }
    if (threadIdx.x == 0) cnt[0] = (float)sh[0];
}

__global__ void bkpart_k(const float* __restrict__ dy, const float* __restrict__ h1,
                         const float* __restrict__ mean, const float* __restrict__ rstd,
                         float* __restrict__ Abk, float* __restrict__ Bbk)
{
    const int bk = blockIdx.x;
    const int b = bk >> 9, k = bk & 511, g = k >> 6;
    const float* pd = dy + (size_t)bk * SP;
    const float* ph = h1 + (size_t)bk * SP;
    const float m = mean[b * GRP + g], r = rstd[b * GRP + g];
    float s1 = 0.f, s2 = 0.f;
    for (int i = threadIdx.x; i < SP; i += 128) {
        float d = pd[i];
        float xh = (ph[i] - m) * r;
        s1 += d; s2 += d * xh;
    }
    __shared__ float sh1[128], sh2[128];
    sh1[threadIdx.x] = s1; sh2[threadIdx.x] = s2;
    __syncthreads();
    for (int o = 64; o > 0; o >>= 1) {
        if (threadIdx.x < o) { sh1[threadIdx.x] += sh1[threadIdx.x + o];
                               sh2[threadIdx.x] += sh2[threadIdx.x + o]; }
        __syncthreads();
    }
    if (threadIdx.x == 0) { Abk[bk] = sh1[0]; Bbk[bk] = sh2[0]; }
}

__global__ void gn_update_k(const float* __restrict__ Abk, const float* __restrict__ Bbk,
                            const float* __restrict__ gnw, const float* __restrict__ gnb,
                            float* __restrict__ gnwf, float* __restrict__ gnbf)
{
    const int k = threadIdx.x;
    float ga = 0.f, gw = 0.f;
    for (int b = 0; b < BN; b++) { ga += Abk[b * HID + k]; gw += Bbk[b * HID + k]; }
    gnbf[k] = gnb[k] - LRf * ga;
    gnwf[k] = gnw[k] - LRf * gw;
}

__global__ void s12_k(const float* __restrict__ Abk, const float* __restrict__ Bbk,
                      const float* __restrict__ gnw, float* __restrict__ s1,
                      float* __restrict__ s2)
{
    const int bg = threadIdx.x;
    const int b = bg >> 3, g = bg & 7;
    float a = 0.f, c = 0.f;
    for (int l = 0; l < GC; l++) {
        int k = g * GC + l;
        float w = gnw[k];
        a += w * Abk[b * HID + k];
        c += w * Bbk[b * HID + k];
    }
    s1[bg] = a; s2[bg] = c;
}

__global__ void dh1_k(float* __restrict__ dy, const float* __restrict__ h1,
                      const float* __restrict__ mean, const float* __restrict__ rstd,
                      const float* __restrict__ gnw, const float* __restrict__ s1,
                      const float* __restrict__ s2)
{
    size_t i4 = (size_t)blockIdx.x * 256 + threadIdx.x;
    size_t base = i4 * 4;
    int k  = (int)((base >> 12) & 511);
    int bg = (int)(base >> 18);
    float m = mean[bg], r = rstd[bg], w = gnw[k];
    const float invM = 1.0f / (GC * SP);
    float a = s1[bg] * invM, c = s2[bg] * invM;
    float4 d = ((const float4*)dy)[i4];
    float4 h = ((const float4*)h1)[i4];
    d.x = r * (w * d.x - a - (h.x - m) * r * c);
    d.y = r * (w * d.y - a - (h.y - m) * r * c);
    d.z = r * (w * d.z - a - (h.z - m) * r * c);
    d.w = r * (w * d.w - a - (h.w - m) * r * c);
    ((float4*)dy)[i4] = d;
}

__global__ void reduce_update_k(const float* __restrict__ P, const float* __restrict__ w,
                                float* __restrict__ wf, int MN)
{
    int i = blockIdx.x * 256 + threadIdx.x;
    if (i < MN) {
        float s = 0.f;
        for (int b = 0; b < BN; b++) s += P[(size_t)b * MN + i];
        wf[i] = w[i] - LRf * s;
    }
}

__global__ void pooled_k(const float* __restrict__ x, float* __restrict__ pooled)
{
    const int bc = blockIdx.x;
    const float* p = x + (size_t)bc * SP;
    float s = 0.f;
    for (int i = threadIdx.x; i < SP; i += 128) s += p[i];
    __shared__ float sh[128];
    sh[threadIdx.x] = s;
    __syncthreads();
    for (int o = 64; o > 0; o >>= 1) {
        if (threadIdx.x < o) sh[threadIdx.x] += sh[threadIdx.x + o];
        __syncthreads();
    }
    if (threadIdx.x == 0) pooled[bc] = sh[0] * (1.0f / SP);
}

__global__ void gate_k(const float* __restrict__ pooled, const float* __restrict__ gw1,
                       const float* __restrict__ gb1, const float* __restrict__ gw2,
                       const float* __restrict__ gb2, float* __restrict__ gate)
{
    const int b = blockIdx.x;
    const int j = threadIdx.x;
    float acc = gb1[j];
    for (int c = 0; c < CC; c++) acc += pooled[b * CC + c] * gw1[j * CC + c];
    __shared__ float sh[64];
    sh[j] = geluf(acc) * gw2[j];
    __syncthreads();
    for (int o = 32; o > 0; o >>= 1) {
        if (j < o) sh[j] += sh[j + o];
        __syncthreads();
    }
    if (j == 0) gate[b] = 1.0f / (1.0f + expf(-(sh[0] + gb2[0])));
}

// ---------------------------------------------------------------------------
// Launch
// ---------------------------------------------------------------------------
extern "C" void kernel_launch(void* const* d_in, const int* in_sizes, int n_in,
                              void* d_out, int out_size)
{
    const float* x    = (const float*)d_in[0];
    const int*   mask = (const int*)  d_in[1];
    const float* w1   = (const float*)d_in[2];
    const float* gnw  = (const float*)d_in[3];
    const float* gnb  = (const float*)d_in[4];
    const float* w2   = (const float*)d_in[5];
    const float* rc1  = (const float*)d_in[6];
    const float* rc2  = (const float*)d_in[7];
    const float* gw1  = (const float*)d_in[8];
    const float* gb1  = (const float*)d_in[9];
    const float* gw2  = (const float*)d_in[10];
    const float* gb2  = (const float*)d_in[11];
    const float* rs   = (const float*)d_in[12];
    float* out = (float*)d_out;
    (void)in_sizes; (void)n_in; (void)out_size;

    float *h1, *act, *dyb, *z, *rdiff, *dz, *pre, *dpre;
    float *meanb, *rstdb, *cm, *cv, *cnt, *Abk, *Bbk, *s1, *s2;
    float *gnwf, *gnbf, *w1f, *w2f, *pw1, *pw2, *pooled, *gate;
    cudaGetSymbolAddress((void**)&h1,    g_h1);
    cudaGetSymbolAddress((void**)&act,   g_act);
    cudaGetSymbolAddress((void**)&dyb,   g_dy);
    cudaGetSymbolAddress((void**)&z,     g_z);
    cudaGetSymbolAddress((void**)&rdiff, g_rdiff);
    cudaGetSymbolAddress((void**)&dz,    g_dz);
    cudaGetSymbolAddress((void**)&pre,   g_pre);
    cudaGetSymbolAddress((void**)&dpre,  g_dpre);
    cudaGetSymbolAddress((void**)&meanb, g_mean);
    cudaGetSymbolAddress((void**)&rstdb, g_rstd);
    cudaGetSymbolAddress((void**)&cm,    g_cm);
    cudaGetSymbolAddress((void**)&cv,    g_cv);
    cudaGetSymbolAddress((void**)&cnt,   g_cnt);
    cudaGetSymbolAddress((void**)&Abk,   g_Abk);
    cudaGetSymbolAddress((void**)&Bbk,   g_Bbk);
    cudaGetSymbolAddress((void**)&s1,    g_s1);
    cudaGetSymbolAddress((void**)&s2,    g_s2);
    cudaGetSymbolAddress((void**)&gnwf,  g_gnwf);
    cudaGetSymbolAddress((void**)&gnbf,  g_gnbf);
    cudaGetSymbolAddress((void**)&w1f,   g_w1f);
    cudaGetSymbolAddress((void**)&w2f,   g_w2f);
    cudaGetSymbolAddress((void**)&pw1,   g_pw1);
    cudaGetSymbolAddress((void**)&pw2,   g_pw2);
    cudaGetSymbolAddress((void**)&pooled,g_pool);
    cudaGetSymbolAddress((void**)&gate,  g_gate);

    // --- gate path (independent of everything but x) ---
    pooled_k<<<BN * CC, 128>>>(x, pooled);
    gate_k<<<BN, 64>>>(pooled, gw1, gb1, gw2, gb2, gate);
    mask_count_k<<<1, 256>>>(mask, cnt);

    // --- forward modifier at original params ---
    { EpiArgs ea = {};
      gemmX<128, 256, false, PRE_NONE, EPI_STORE><<<dim3(32, 4, BN), 256>>>(w1, x, h1, HID, mask, ea); }
    gn_stats_k<<<BN * GRP, 256>>>(h1, meanb, rstdb);
    gn_gelu_k<<<65536, 256>>>(h1, meanb, rstdb, gnw, gnb, act);
    { EpiArgs ea = {}; ea.x = x;
      gemmX<128, 512, false, PRE_NONE, EPI_ADDX><<<dim3(32, 2, BN), 256>>>(w2, act, z, CC, mask, ea); }

    // --- surprise loss forward + dz ---
    zstats_k<<<CC, 256>>>(z, cm, cv);
    { EpiArgs ea = {};
      gemmX<64, 256, false, PRE_MASK, EPI_STORE><<<dim3(32, 1, BN), 256>>>(rc1, z, pre, BOT, mask, ea); }
    { EpiArgs ea = {}; ea.z = z;
      gemmX<128, 64, false, PRE_GELU, EPI_RDIFF><<<dim3(32, 2, BN), 256>>>(rc2, pre, rdiff, CC, mask, ea); }
    { EpiArgs ea = {}; ea.pre = pre; ea.cnt = cnt;
      gemmX<64, 256, true, PRE_NONE, EPI_DPRE><<<dim3(32, 1, BN), 256>>>(rc2, rdiff, dpre, BOT, mask, ea); }
    { EpiArgs ea = {}; ea.rdiff = rdiff; ea.z = z; ea.cm = cm; ea.cv = cv; ea.cnt = cnt;
      gemmX<128, 64, true, PRE_NONE, EPI_DZ><<<dim3(32, 2, BN), 256>>>(rc1, dpre, dz, CC, mask, ea); }

    // --- backward through modifier ---
    { EpiArgs ea = {}; ea.h1 = h1; ea.mean = meanb; ea.rstd = rstdb; ea.gnw = gnw; ea.gnb = gnb;
      gemmX<128, 256, true, PRE_NONE, EPI_DY><<<dim3(32, 4, BN), 256>>>(w2, dz, dyb, HID, mask, ea); }
    bkpart_k<<<BN * HID, 128>>>(dyb, h1, meanb, rstdb, Abk, Bbk);
    gn_update_k<<<1, HID>>>(Abk, Bbk, gnw, gnb, gnwf, gnbf);
    s12_k<<<1, BN * GRP>>>(Abk, Bbk, gnw, s1, s2);
    dh1_k<<<65536, 256>>>(dyb, h1, meanb, rstdb, gnw, s1, s2);

    gemm_ntX<<<dim3(2, 4, BN), 256>>>(dyb, HID, x, CC, pw1, HID, CC);
    reduce_update_k<<<512, 256>>>(pw1, w1, w1f, HID * CC);
    gemm_ntX<<<dim3(4, 2, BN), 256>>>(dz, CC, act, HID, pw2, CC, HID);
    reduce_update_k<<<512, 256>>>(pw2, w2, w2f, CC * HID);

    // --- final modifier at fast weights + residual/gate epilogue ---
    { EpiArgs ea = {};
      gemmX<128, 256, false, PRE_NONE, EPI_STORE><<<dim3(32, 4, BN), 256>>>(w1f, x, h1, HID, mask, ea); }
    gn_stats_k<<<BN * GRP, 256>>>(h1, meanb, rstdb);
    gn_gelu_k<<<65536, 256>>>(h1, meanb, rstdb, gnwf, gnbf, act);
    { EpiArgs ea = {}; ea.x = x; ea.gate = gate; ea.rs = rs;
      gemmX<128, 512, false, PRE_NONE, EPI_FINAL><<<dim3(32, 2, BN), 256>>>(w2f, act, out, CC, mask, ea); }
}

// round 15
// speedup vs baseline: 3.8003x; 2.9983x over previous
#include <cuda_runtime.h>
#include <cuda_bf16.h>
#include <math.h>
#include <stdint.h>

#define BN   32
#define CC   256
#define HID  512
#define SP   4096
#define GRP  8
#define GC   64
#define BOT  64
#define NTOT (BN*SP)
#define LRf  0.005f

// fp32 scratch
__device__ float g_h1   [(size_t)BN*HID*SP];
__device__ float g_dy   [(size_t)BN*HID*SP];
__device__ float g_z    [(size_t)BN*CC*SP];
__device__ float g_rdiff[(size_t)BN*CC*SP];
__device__ float g_dz   [(size_t)BN*CC*SP];
__device__ float g_pre  [(size_t)BN*BOT*SP];
__device__ float g_dpre [(size_t)BN*BOT*SP];
__device__ float g_mean [BN*GRP];
__device__ float g_rstd [BN*GRP];
__device__ float g_cm   [CC];
__device__ float g_cv   [CC];
__device__ float g_cnt  [1];
__device__ float g_Abk  [BN*HID];
__device__ float g_Bbk  [BN*HID];
__device__ float g_s1   [BN*GRP];
__device__ float g_s2   [BN*GRP];
__device__ float g_gnwf [HID];
__device__ float g_gnbf [HID];
__device__ float g_w1f  [HID*CC];
__device__ float g_w2f  [CC*HID];
__device__ float g_pw1  [(size_t)BN*HID*CC];
__device__ float g_pw2  [(size_t)BN*CC*HID];
__device__ float g_pool [BN*CC];
__device__ float g_gate [BN];
// bf16 operands
__device__ __nv_bfloat16 g_bx   [(size_t)BN*SP*CC];
__device__ __nv_bfloat16 g_bxn  [(size_t)BN*CC*SP];
__device__ __nv_bfloat16 g_bact [(size_t)BN*SP*HID];
__device__ __nv_bfloat16 g_bactn[(size_t)BN*HID*SP];
__device__ __nv_bfloat16 g_bzm  [(size_t)BN*SP*CC];
__device__ __nv_bfloat16 g_bgp  [(size_t)BN*SP*BOT];
__device__ __nv_bfloat16 g_brd  [(size_t)BN*SP*CC];
__device__ __nv_bfloat16 g_bdp  [(size_t)BN*SP*BOT];
__device__ __nv_bfloat16 g_bdz  [(size_t)BN*SP*CC];
__device__ __nv_bfloat16 g_bdzn [(size_t)BN*CC*SP];
__device__ __nv_bfloat16 g_bdyn [(size_t)BN*HID*SP];
// bf16 weights
__device__ __nv_bfloat16 g_wb1  [HID*CC];
__device__ __nv_bfloat16 g_wb2  [CC*HID];
__device__ __nv_bfloat16 g_rb1p [128*CC];
__device__ __nv_bfloat16 g_rb2  [CC*BOT];
__device__ __nv_bfloat16 g_rb2tp[128*CC];
__device__ __nv_bfloat16 g_rb1t [CC*BOT];
__device__ __nv_bfloat16 g_wb2t [HID*CC];
__device__ __nv_bfloat16 g_wb1f [HID*CC];
__device__ __nv_bfloat16 g_wb2f [CC*HID];

__device__ __forceinline__ float geluf(float x) {
    return 0.5f * x * (1.0f + erff(x * 0.70710678118654752f));
}
__device__ __forceinline__ float gelugradf(float x) {
    float cdf = 0.5f * (1.0f + erff(x * 0.70710678118654752f));
    float pdf = 0.3989422804014327f * expf(-0.5f * x * x);
    return cdf + x * pdf;
}

__device__ __forceinline__ uint32_t s2u(const void* p) {
    uint32_t a;
    asm("{ .reg .u64 t; cvta.to.shared.u64 t, %1; cvt.u32.u64 %0, t; }" : "=r"(a) : "l"(p));
    return a;
}
__device__ __forceinline__ void ldsm4(uint32_t* r, uint32_t addr) {
    asm volatile("ldmatrix.sync.aligned.m8n8.x4.shared.b16 {%0,%1,%2,%3}, [%4];"
                 : "=r"(r[0]), "=r"(r[1]), "=r"(r[2]), "=r"(r[3]) : "r"(addr));
}
__device__ __forceinline__ void mma16816(float* c, const uint32_t* a, uint32_t b0, uint32_t b1) {
    asm volatile("mma.sync.aligned.m16n8k16.row.col.f32.bf16.bf16.f32 "
                 "{%0,%1,%2,%3}, {%4,%5,%6,%7}, {%8,%9}, {%0,%1,%2,%3};"
                 : "+f"(c[0]), "+f"(c[1]), "+f"(c[2]), "+f"(c[3])
                 : "r"(a[0]), "r"(a[1]), "r"(a[2]), "r"(a[3]), "r"(b0), "r"(b1));
}

enum { EPI_STORE = 0, EPI_ADDX = 1, EPI_RDIFF = 2, EPI_DPRE = 3,
       EPI_DZ = 4, EPI_DY = 5, EPI_FINAL = 6, EPI_NT = 7 };

struct EpiArgs {
    const float *x, *z, *rdiff, *pre, *cm, *cv, *cnt, *h1, *mean, *rstd, *gnw, *gnb, *gate, *rs;
};

#define PITCH 72   // bf16 per smem row (144 B) — conflict-free ldmatrix

// mma.sync GEMM: D[b][m,n] = sum_k A[m,k]*Bt[b][n,k], bf16 in, f32 out.
// CTA tile 128x128, K chunk 64. 8 warps: 4 over M (32 rows), 2 over N (64 cols).
template<int EPI, bool ABATCH>
__global__ void __launch_bounds__(256)
mmas(const __nv_bfloat16* __restrict__ A, int lda, size_t aB,
     const __nv_bfloat16* __restrict__ Bt, int ldb, size_t bB,
     float* __restrict__ out, int Mlog, int ldout, size_t outB,
     int nchunks, const int* __restrict__ mask, EpiArgs ea)
{
    __shared__ __align__(16) __nv_bfloat16 As[128 * PITCH];
    __shared__ __align__(16) __nv_bfloat16 Bs[128 * PITCH];

    const int tid = threadIdx.x, wid = tid >> 5, lane = tid & 31;
    const int wm = wid & 3, wn = wid >> 2;
    const int n0 = blockIdx.x * 128, m0 = blockIdx.y * 128, b = blockIdx.z;

    const char* Ab = (const char*)(A + (ABATCH ? (size_t)b * aB : 0));
    const char* Bb = (const char*)(Bt + (size_t)b * bB);
    const uint32_t aU = s2u(As), bU = s2u(Bs);

    float acc[2][8][4];
    #pragma unroll
    for (int i = 0; i < 2; i++)
        #pragma unroll
        for (int j = 0; j < 8; j++)
            #pragma unroll
            for (int k = 0; k < 4; k++) acc[i][j][k] = 0.0f;

    for (int kc = 0; kc < nchunks; kc++) {
        const size_t kof = (size_t)kc * 128;          // 64 bf16 = 128 B
        #pragma unroll
        for (int i = 0; i < 4; i++) {
            int s_ = tid + i * 256, row = s_ >> 3, seg = s_ & 7;  // 128 rows x 8 x 16B
            *(uint4*)((char*)As + row * (PITCH * 2) + seg * 16) =
                *(const uint4*)(Ab + (size_t)(m0 + row) * lda * 2 + kof + seg * 16);
            *(uint4*)((char*)Bs + row * (PITCH * 2) + seg * 16) =
                *(const uint4*)(Bb + (size_t)(n0 + row) * ldb * 2 + kof + seg * 16);
        }
        __syncthreads();
        #pragma unroll
        for (int kk = 0; kk < 4; kk++) {              // 4 x k16
            const uint32_t koff = kk * 32 + (lane >> 4) * 16;
            uint32_t af[2][4];
            #pragma unroll
            for (int mi = 0; mi < 2; mi++)
                ldsm4(af[mi], aU + (wm * 32 + mi * 16 + (lane & 15)) * (PITCH * 2) + koff);
            uint32_t bf[4][4];
            #pragma unroll
            for (int nq = 0; nq < 4; nq++)
                ldsm4(bf[nq], bU + (wn * 64 + nq * 16 + (lane & 15)) * (PITCH * 2) + koff);
            // x4 result order: r0=(rows0-7,k0-7) r1=(rows8-15,k0-7) r2=(rows0-7,k8-15) r3=(rows8-15,k8-15)
            #pragma unroll
            for (int mi = 0; mi < 2; mi++)
                #pragma unroll
                for (int nj = 0; nj < 8; nj++) {
                    const int nq = nj >> 1, hi = nj & 1;
                    mma16816(acc[mi][nj], af[mi], bf[nq][hi], bf[nq][2 + hi]);
                }
        }
        __syncthreads();
    }

    // epilogue: C frag c0,c1 = (row g, col tg*2,+1); c2,c3 = (row g+8)
    const int g = lane >> 2, tg = lane & 3;
    const float sc = (EPI == EPI_DPRE || EPI == EPI_DZ)
                   ? 2.0f / (ea.cnt[0] * 256.0f + 1e-8f) : 0.0f;
    #pragma unroll
    for (int mi = 0; mi < 2; mi++) {
        #pragma unroll
        for (int h = 0; h < 2; h++) {
            const int row = m0 + wm * 32 + mi * 16 + g + h * 8;
            if (row >= Mlog) continue;
            #pragma unroll
            for (int nj = 0; nj < 8; nj++) {
                const int col = n0 + wn * 64 + nj * 8 + tg * 2;
                const size_t gi = (size_t)b * outB + (size_t)row * ldout + col;
                float v0 = acc[mi][nj][h * 2 + 0];
                float v1 = acc[mi][nj][h * 2 + 1];
                if (EPI == EPI_ADDX) {
                    float2 xv = *(const float2*)(ea.x + gi);
                    v0 += xv.x; v1 += xv.y;
                } else if (EPI == EPI_RDIFF) {
                    int2 mk = *(const int2*)(mask + b * SP + col);
                    float2 zv = *(const float2*)(ea.z + gi);
                    v0 = (v0 - zv.x) * (1.0f - (float)mk.x);
                    v1 = (v1 - zv.y) * (1.0f - (float)mk.y);
                } else if (EPI == EPI_DPRE) {
                    float2 pv = *(const float2*)(ea.pre + gi);
                    v0 = v0 * gelugradf(pv.x) * sc;
                    v1 = v1 * gelugradf(pv.y) * sc;
                } else if (EPI == EPI_DZ) {
                    int2 mk = *(const int2*)(mask + b * SP + col);
                    float2 zv = *(const float2*)(ea.z + gi);
                    float2 rv = *(const float2*)(ea.rdiff + gi);
                    float cmc = ea.cm[row];
                    float cvs = ea.cv[row] * (1.0f / (1.0f + 1e-8f));
                    float t1 = 2.0f * cmc * (1.0f / (256.0f * 131072.0f));
                    float t2 = 4.0f * (cvs - 1.0f) * (1.0f / (256.0f * 131071.0f))
                             * (1.0f / (1.0f + 1e-8f));
                    v0 = (float)mk.x * v0 - sc * rv.x + 0.1f * (t1 + t2 * (zv.x - cmc));
                    v1 = (float)mk.y * v1 - sc * rv.y + 0.1f * (t1 + t2 * (zv.y - cmc));
                } else if (EPI == EPI_DY) {
                    int gg = row >> 6;
                    float mn = ea.mean[b * GRP + gg], rsd = ea.rstd[b * GRP + gg];
                    float w = ea.gnw[row], bb = ea.gnb[row];
                    float2 hv = *(const float2*)(ea.h1 + gi);
                    v0 *= gelugradf((hv.x - mn) * rsd * w + bb);
                    v1 *= gelugradf((hv.y - mn) * rsd * w + bb);
                } else if (EPI == EPI_FINAL) {
                    float gt = ea.rs[0] * ea.gate[b];
                    float2 xv = *(const float2*)(ea.x + gi);
                    v0 = xv.x + gt * v0; v1 = xv.y + gt * v1;
                }
                *(float2*)(out + gi) = make_float2(v0, v1);
            }
        }
    }
}

// Transpose+convert fp32 [b][C][s] -> bf16 [b][s][C]; OP: 0 none, 1 mask, 2 gelu, 3 GN+gelu.
template<int C, int OP, bool DUAL>
__global__ void __launch_bounds__(256)
tconv_k(const float* __restrict__ src, __nv_bfloat16* __restrict__ dT,
        __nv_bfloat16* __restrict__ dN, const int* __restrict__ mask,
        const float* __restrict__ mean, const float* __restrict__ rstd,
        const float* __restrict__ gnw, const float* __restrict__ gnb)
{
    __shared__ float t[64][65];
    const int tid = threadIdx.x;
    const int b = blockIdx.z, s0 = blockIdx.x * 64, c0 = blockIdx.y * 64;
    const int sc = (tid & 15) * 4, rc = tid >> 4;
    #pragma unroll
    for (int p = 0; p < 4; p++) {
        int cl = rc + 16 * p, c = c0 + cl;
        float4 v = *(const float4*)(src + ((size_t)b * C + c) * SP + s0 + sc);
        if (OP == 1) {
            int4 mk = *(const int4*)(mask + b * SP + s0 + sc);
            v.x *= (float)mk.x; v.y *= (float)mk.y; v.z *= (float)mk.z; v.w *= (float)mk.w;
        } else if (OP == 2) {
            v.x = geluf(v.x); v.y = geluf(v.y); v.z = geluf(v.z); v.w = geluf(v.w);
        } else if (OP == 3) {
            int bg = b * GRP + (c >> 6);
            float m = mean[bg], r = rstd[bg], w = gnw[c], bb = gnb[c];
            v.x = geluf((v.x - m) * r * w + bb); v.y = geluf((v.y - m) * r * w + bb);
            v.z = geluf((v.z - m) * r * w + bb); v.w = geluf((v.w - m) * r * w + bb);
        }
        t[cl][sc] = v.x; t[cl][sc + 1] = v.y; t[cl][sc + 2] = v.z; t[cl][sc + 3] = v.w;
        if (DUAL) {
            __nv_bfloat162 lo = __floats2bfloat162_rn(v.x, v.y);
            __nv_bfloat162 hi = __floats2bfloat162_rn(v.z, v.w);
            uint2 pk; pk.x = *(uint32_t*)&lo; pk.y = *(uint32_t*)&hi;
            *(uint2*)(dN + ((size_t)b * C + c) * SP + s0 + sc) = pk;
        }
    }
    __syncthreads();
    const int cc = (tid & 31) * 2, sr = tid >> 5;
    #pragma unroll
    for (int p = 0; p < 8; p++) {
        int sl = sr + 8 * p;
        __nv_bfloat162 o = __floats2bfloat162_rn(t[cc][sl], t[cc + 1][sl]);
        *(__nv_bfloat162*)(dT + ((size_t)b * SP + s0 + sl) * C + c0 + cc) = o;
    }
}

// Weight convert, optional transpose-read (src stride srs) + zero-pad rows >= Msrc.
__global__ void wconv_k(const float* __restrict__ src, __nv_bfloat16* __restrict__ dst,
                        int M, int K, int Msrc, int srs, int T)
{
    int i = blockIdx.x * 256 + threadIdx.x;
    if (i < M * K) {
        int m = i / K, k = i % K;
        float v = 0.0f;
        if (m < Msrc) v = T ? src[(size_t)k * srs + m] : src[(size_t)m * K + k];
        dst[i] = __float2bfloat16_rn(v);
    }
}

__global__ void gn_stats_k(const float* __restrict__ h, float* __restrict__ mean,
                           float* __restrict__ rstd)
{
    const int bg = blockIdx.x;
    const float* p = h + (size_t)bg * (GC * SP);
    float s = 0.f, ss = 0.f;
    for (int i = threadIdx.x; i < GC * SP; i += 256) { float v = p[i]; s += v; ss += v * v; }
    __shared__ float sh1[256], sh2[256];
    sh1[threadIdx.x] = s; sh2[threadIdx.x] = ss;
    __syncthreads();
    for (int o = 128; o > 0; o >>= 1) {
        if (threadIdx.x < o) { sh1[threadIdx.x] += sh1[threadIdx.x + o];
                               sh2[threadIdx.x] += sh2[threadIdx.x + o]; }
        __syncthreads();
    }
    if (threadIdx.x == 0) {
        float m = sh1[0] * (1.0f / (GC * SP));
        float var = sh2[0] * (1.0f / (GC * SP)) - m * m;
        mean[bg] = m; rstd[bg] = rsqrtf(var + 1e-5f);
    }
}

__global__ void zstats_k(const float* __restrict__ z, float* __restrict__ cm,
                         float* __restrict__ cv)
{
    const int c = blockIdx.x;
    float s = 0.f, ss = 0.f;
    for (int b = 0; b < BN; b++) {
        const float* p = z + (size_t)b * CC * SP + (size_t)c * SP;
        for (int i = threadIdx.x; i < SP; i += 256) { float v = p[i]; s += v; ss += v * v; }
    }
    __shared__ float sh1[256], sh2[256];
    sh1[threadIdx.x] = s; sh2[threadIdx.x] = ss;
    __syncthreads();
    for (int o = 128; o > 0; o >>= 1) {
        if (threadIdx.x < o) { sh1[threadIdx.x] += sh1[threadIdx.x + o];
                               sh2[threadIdx.x] += sh2[threadIdx.x + o]; }
        __syncthreads();
    }
    if (threadIdx.x == 0) {
        float m = sh1[0] * (1.0f / NTOT);
        cm[c] = m;
        cv[c] = (sh2[0] - (float)NTOT * m * m) * (1.0f / (NTOT - 1));
    }
}

__global__ void mask_count_k(const int* __restrict__ mask, float* __restrict__ cnt)
{
    int s = 0;
    for (int i = threadIdx.x; i < NTOT; i += 256) s += 1 - mask[i];
    __shared__ int sh[256];
    sh[threadIdx.x] = s;
    __syncthreads();
    for (int o = 128; o > 0; o >>= 1) {
        if (threadIdx.x < o) sh[threadIdx.x] += sh[threadIdx.x + o];
        __syncthreads();
    }
    if (threadIdx.x == 0) cnt[0] = (float)sh[0];
}

__global__ void bkpart_k(const float* __restrict__ dy, const float* __restrict__ h1,
                         const float* __restrict__ mean, const float* __restrict__ rstd,
                         float* __restrict__ Abk, float* __restrict__ Bbk)
{
    const int bk = blockIdx.x;
    const int b = bk >> 9, k = bk & 511, g = k >> 6;
    const float* pd = dy + (size_t)bk * SP;
    const float* ph = h1 + (size_t)bk * SP;
    const float m = mean[b * GRP + g], r = rstd[b * GRP + g];
    float s1 = 0.f, s2 = 0.f;
    for (int i = threadIdx.x; i < SP; i += 128) {
        float d = pd[i], xh = (ph[i] - m) * r;
        s1 += d; s2 += d * xh;
    }
    __shared__ float sh1[128], sh2[128];
    sh1[threadIdx.x] = s1; sh2[threadIdx.x] = s2;
    __syncthreads();
    for (int o = 64; o > 0; o >>= 1) {
        if (threadIdx.x < o) { sh1[threadIdx.x] += sh1[threadIdx.x + o];
                               sh2[threadIdx.x] += sh2[threadIdx.x + o]; }
        __syncthreads();
    }
    if (threadIdx.x == 0) { Abk[bk] = sh1[0]; Bbk[bk] = sh2[0]; }
}

__global__ void gn_update_k(const float* __restrict__ Abk, const float* __restrict__ Bbk,
                            const float* __restrict__ gnw, const float* __restrict__ gnb,
                            float* __restrict__ gnwf, float* __restrict__ gnbf)
{
    const int k = threadIdx.x;
    float ga = 0.f, gw = 0.f;
    for (int b = 0; b < BN; b++) { ga += Abk[b * HID + k]; gw += Bbk[b * HID + k]; }
    gnbf[k] = gnb[k] - LRf * ga;
    gnwf[k] = gnw[k] - LRf * gw;
}

__global__ void s12_k(const float* __restrict__ Abk, const float* __restrict__ Bbk,
                      const float* __restrict__ gnw, float* __restrict__ s1,
                      float* __restrict__ s2)
{
    const int bg = threadIdx.x;
    const int b = bg >> 3, g = bg & 7;
    float a = 0.f, c = 0.f;
    for (int l = 0; l < GC; l++) {
        int k = g * GC + l;
        float w = gnw[k];
        a += w * Abk[b * HID + k];
        c += w * Bbk[b * HID + k];
    }
    s1[bg] = a; s2[bg] = c;
}

// GN input-grad -> bf16 natural layout (only consumer is the NT GEMM).
__global__ void dh1_bf_k(const float* __restrict__ dy, const float* __restrict__ h1,
                         const float* __restrict__ mean, const float* __restrict__ rstd,
                         const float* __restrict__ gnw, const float* __restrict__ s1,
                         const float* __restrict__ s2, __nv_bfloat16* __restrict__ outb)
{
    size_t i4 = (size_t)blockIdx.x * 256 + threadIdx.x;
    size_t base = i4 * 4;
    int k  = (int)((base >> 12) & 511);
    int bg = (int)(base >> 18);
    float m = mean[bg], r = rstd[bg], w = gnw[k];
    const float invM = 1.0f / (GC * SP);
    float a = s1[bg] * invM, c = s2[bg] * invM;
    float4 d = ((const float4*)dy)[i4];
    float4 h = ((const float4*)h1)[i4];
    d.x = r * (w * d.x - a - (h.x - m) * r * c);
    d.y = r * (w * d.y - a - (h.y - m) * r * c);
    d.z = r * (w * d.z - a - (h.z - m) * r * c);
    d.w = r * (w * d.w - a - (h.w - m) * r * c);
    __nv_bfloat162 lo = __floats2bfloat162_rn(d.x, d.y);
    __nv_bfloat162 hi = __floats2bfloat162_rn(d.z, d.w);
    uint2 pk; pk.x = *(uint32_t*)&lo; pk.y = *(uint32_t*)&hi;
    *(uint2*)(outb + base) = pk;
}

__global__ void reduce_update_k(const float* __restrict__ P, const float* __restrict__ w,
                                float* __restrict__ wf, int MN)
{
    int i = blockIdx.x * 256 + threadIdx.x;
    if (i < MN) {
        float s = 0.f;
        for (int b = 0; b < BN; b++) s += P[(size_t)b * MN + i];
        wf[i] = w[i] - LRf * s;
    }
}

__global__ void pooled_k(const float* __restrict__ x, float* __restrict__ pooled)
{
    const int bc = blockIdx.x;
    const float* p = x + (size_t)bc * SP;
    float s = 0.f;
    for (int i = threadIdx.x; i < SP; i += 128) s += p[i];
    __shared__ float sh[128];
    sh[threadIdx.x] = s;
    __syncthreads();
    for (int o = 64; o > 0; o >>= 1) {
        if (threadIdx.x < o) sh[threadIdx.x] += sh[threadIdx.x + o];
        __syncthreads();
    }
    if (threadIdx.x == 0) pooled[bc] = sh[0] * (1.0f / SP);
}

__global__ void gate_k(const float* __restrict__ pooled, const float* __restrict__ gw1,
                       const float* __restrict__ gb1, const float* __restrict__ gw2,
                       const float* __restrict__ gb2, float* __restrict__ gate)
{
    const int b = blockIdx.x, j = threadIdx.x;
    float acc = gb1[j];
    for (int c = 0; c < CC; c++) acc += pooled[b * CC + c] * gw1[j * CC + c];
    __shared__ float sh[64];
    sh[j] = geluf(acc) * gw2[j];
    __syncthreads();
    for (int o = 32; o > 0; o >>= 1) {
        if (j < o) sh[j] += sh[j + o];
        __syncthreads();
    }
    if (j == 0) gate[b] = 1.0f / (1.0f + expf(-(sh[0] + gb2[0])));
}

#define GSA(v, s) cudaGetSymbolAddress((void**)&v, s)

extern "C" void kernel_launch(void* const* d_in, const int* in_sizes, int n_in,
                              void* d_out, int out_size)
{
    const float* x    = (const float*)d_in[0];
    const int*   mask = (const int*)  d_in[1];
    const float* w1   = (const float*)d_in[2];
    const float* gnw  = (const float*)d_in[3];
    const float* gnb  = (const float*)d_in[4];
    const float* w2   = (const float*)d_in[5];
    const float* rc1  = (const float*)d_in[6];
    const float* rc2  = (const float*)d_in[7];
    const float* gw1  = (const float*)d_in[8];
    const float* gb1  = (const float*)d_in[9];
    const float* gw2  = (const float*)d_in[10];
    const float* gb2  = (const float*)d_in[11];
    const float* rs   = (const float*)d_in[12];
    float* out = (float*)d_out;
    (void)in_sizes; (void)n_in; (void)out_size;

    float *h1, *dyb, *z, *rdiff, *dz, *pre, *dpre, *meanb, *rstdb, *cm, *cv, *cnt;
    float *Abk, *Bbk, *s1, *s2, *gnwf, *gnbf, *w1f, *w2f, *pw1, *pw2, *pooled, *gate;
    __nv_bfloat16 *bx, *bxn, *bact, *bactn, *bzm, *bgp, *brd, *bdp, *bdz, *bdzn, *bdyn;
    __nv_bfloat16 *wb1, *wb2, *rb1p, *rb2, *rb2tp, *rb1t, *wb2t, *wb1f, *wb2f;
    GSA(h1, g_h1); GSA(dyb, g_dy); GSA(z, g_z); GSA(rdiff, g_rdiff); GSA(dz, g_dz);
    GSA(pre, g_pre); GSA(dpre, g_dpre); GSA(meanb, g_mean); GSA(rstdb, g_rstd);
    GSA(cm, g_cm); GSA(cv, g_cv); GSA(cnt, g_cnt); GSA(Abk, g_Abk); GSA(Bbk, g_Bbk);
    GSA(s1, g_s1); GSA(s2, g_s2); GSA(gnwf, g_gnwf); GSA(gnbf, g_gnbf);
    GSA(w1f, g_w1f); GSA(w2f, g_w2f); GSA(pw1, g_pw1); GSA(pw2, g_pw2);
    GSA(pooled, g_pool); GSA(gate, g_gate);
    GSA(bx, g_bx); GSA(bxn, g_bxn); GSA(bact, g_bact); GSA(bactn, g_bactn);
    GSA(bzm, g_bzm); GSA(bgp, g_bgp); GSA(brd, g_brd); GSA(bdp, g_bdp);
    GSA(bdz, g_bdz); GSA(bdzn, g_bdzn); GSA(bdyn, g_bdyn);
    GSA(wb1, g_wb1); GSA(wb2, g_wb2); GSA(rb1p, g_rb1p); GSA(rb2, g_rb2);
    GSA(rb2tp, g_rb2tp); GSA(rb1t, g_rb1t); GSA(wb2t, g_wb2t);
    GSA(wb1f, g_wb1f); GSA(wb2f, g_wb2f);

    // independent small work
    pooled_k<<<BN * CC, 128>>>(x, pooled);
    gate_k<<<BN, 64>>>(pooled, gw1, gb1, gw2, gb2, gate);
    mask_count_k<<<1, 256>>>(mask, cnt);

    // weight conversions
    wconv_k<<<512, 256>>>(w1,  wb1,  HID, CC, HID, 0, 0);
    wconv_k<<<512, 256>>>(w2,  wb2,  CC, HID, CC, 0, 0);
    wconv_k<<<128, 256>>>(rc1, rb1p, 128, CC, BOT, 0, 0);
    wconv_k<<<64,  256>>>(rc2, rb2,  CC, BOT, CC, 0, 0);
    wconv_k<<<128, 256>>>(rc2, rb2tp, 128, CC, BOT, BOT, 1);
    wconv_k<<<64,  256>>>(rc1, rb1t, CC, BOT, CC, CC, 1);
    wconv_k<<<512, 256>>>(w2,  wb2t, HID, CC, HID, HID, 1);

    // x -> bf16 (T + natural)
    tconv_k<CC, 0, true><<<dim3(64, 4, BN), 256>>>(x, bx, bxn, mask, 0, 0, 0, 0);

    EpiArgs ez = {};
    // h1 = w1 . x
    mmas<EPI_STORE, false><<<dim3(32, 4, BN), 256>>>(wb1, CC, 0, bx, CC, (size_t)SP * CC,
        h1, HID, SP, (size_t)HID * SP, 4, mask, ez);
    gn_stats_k<<<BN * GRP, 256>>>(h1, meanb, rstdb);
    // act = gelu(GN(h1)) -> bf16 T + natural
    tconv_k<HID, 3, true><<<dim3(64, 8, BN), 256>>>(h1, bact, bactn, mask, meanb, rstdb, gnw, gnb);
    // z = w2 . act + x
    { EpiArgs ea = ez; ea.x = x;
      mmas<EPI_ADDX, false><<<dim3(32, 2, BN), 256>>>(wb2, HID, 0, bact, HID, (size_t)SP * HID,
          z, CC, SP, (size_t)CC * SP, 8, mask, ea); }
    zstats_k<<<CC, 256>>>(z, cm, cv);
    // pre = rc1 . (z*mask)
    tconv_k<CC, 1, false><<<dim3(64, 4, BN), 256>>>(z, bzm, 0, mask, 0, 0, 0, 0);
    mmas<EPI_STORE, false><<<dim3(32, 1, BN), 256>>>(rb1p, CC, 0, bzm, CC, (size_t)SP * CC,
        pre, BOT, SP, (size_t)BOT * SP, 4, mask, ez);
    // rdiff = (rc2 . gelu(pre) - z) * inv
    tconv_k<BOT, 2, false><<<dim3(64, 1, BN), 256>>>(pre, bgp, 0, mask, 0, 0, 0, 0);
    { EpiArgs ea = ez; ea.z = z;
      mmas<EPI_RDIFF, false><<<dim3(32, 2, BN), 256>>>(rb2, BOT, 0, bgp, BOT, (size_t)SP * BOT,
          rdiff, CC, SP, (size_t)CC * SP, 1, mask, ea); }
    // dpre = (rc2^T . rdiff) * g'(pre) * sc
    tconv_k<CC, 0, false><<<dim3(64, 4, BN), 256>>>(rdiff, brd, 0, mask, 0, 0, 0, 0);
    { EpiArgs ea = ez; ea.pre = pre; ea.cnt = cnt;
      mmas<EPI_DPRE, false><<<dim3(32, 1, BN), 256>>>(rb2tp, CC, 0, brd, CC, (size_t)SP * CC,
          dpre, BOT, SP, (size_t)BOT * SP, 4, mask, ea); }
    // dz = mask*(rc1^T . dpre) - sc*rdiff + consist
    tconv_k<BOT, 0, false><<<dim3(64, 1, BN), 256>>>(dpre, bdp, 0, mask, 0, 0, 0, 0);
    { EpiArgs ea = ez; ea.rdiff = rdiff; ea.z = z; ea.cm = cm; ea.cv = cv; ea.cnt = cnt;
      mmas<EPI_DZ, false><<<dim3(32, 2, BN), 256>>>(rb1t, BOT, 0, bdp, BOT, (size_t)SP * BOT,
          dz, CC, SP, (size_t)CC * SP, 1, mask, ea); }
    tconv_k<CC, 0, true><<<dim3(64, 4, BN), 256>>>(dz, bdz, bdzn, mask, 0, 0, 0, 0);
    // dy = (w2^T . dz) * g'(GN(h1))
    { EpiArgs ea = ez; ea.h1 = h1; ea.mean = meanb; ea.rstd = rstdb; ea.gnw = gnw; ea.gnb = gnb;
      mmas<EPI_DY, false><<<dim3(32, 4, BN), 256>>>(wb2t, CC, 0, bdz, CC, (size_t)SP * CC,
          dyb, HID, SP, (size_t)HID * SP, 4, mask, ea); }
    bkpart_k<<<BN * HID, 128>>>(dyb, h1, meanb, rstdb, Abk, Bbk);
    gn_update_k<<<1, HID>>>(Abk, Bbk, gnw, gnb, gnwf, gnbf);
    s12_k<<<1, BN * GRP>>>(Abk, Bbk, gnw, s1, s2);
    dh1_bf_k<<<65536, 256>>>(dyb, h1, meanb, rstdb, gnw, s1, s2, bdyn);
    // grad_w1 = dh1 . x^T (split-K over batch, reduce after)
    mmas<EPI_NT, true><<<dim3(2, 4, BN), 256>>>(bdyn, SP, (size_t)HID * SP, bxn, SP,
        (size_t)CC * SP, pw1, HID, CC, (size_t)HID * CC, 64, mask, ez);
    reduce_update_k<<<512, 256>>>(pw1, w1, w1f, HID * CC);
    // grad_w2 = dz . act^T
    mmas<EPI_NT, true><<<dim3(4, 2, BN), 256>>>(bdzn, SP, (size_t)CC * SP, bactn, SP,
        (size_t)HID * SP, pw2, CC, HID, (size_t)CC * HID, 64, mask, ez);
    reduce_update_k<<<512, 256>>>(pw2, w2, w2f, CC * HID);
    wconv_k<<<512, 256>>>(w1f, wb1f, HID, CC, HID, 0, 0);
    wconv_k<<<512, 256>>>(w2f, wb2f, CC, HID, CC, 0, 0);

    // final modifier at fast weights
    mmas<EPI_STORE, false><<<dim3(32, 4, BN), 256>>>(wb1f, CC, 0, bx, CC, (size_t)SP * CC,
        h1, HID, SP, (size_t)HID * SP, 4, mask, ez);
    gn_stats_k<<<BN * GRP, 256>>>(h1, meanb, rstdb);
    tconv_k<HID, 3, false><<<dim3(64, 8, BN), 256>>>(h1, bact, 0, mask, meanb, rstdb, gnwf, gnbf);
    { EpiArgs ea = ez; ea.x = x; ea.gate = gate; ea.rs = rs;
      mmas<EPI_FINAL, false><<<dim3(32, 2, BN), 256>>>(wb2f, HID, 0, bact, HID, (size_t)SP * HID,
          out, CC, SP, (size_t)CC * SP, 8, mask, ea); }
}

// round 16
// speedup vs baseline: 4.4304x; 1.1658x over previous
#include <cuda_runtime.h>
#include <cuda_bf16.h>
#include <math.h>
#include <stdint.h>

#define BN   32
#define CC   256
#define HID  512
#define SP   4096
#define GRP  8
#define GC   64
#define BOT  64
#define NTOT (BN*SP)
#define LRf  0.005f

// fp32 scratch
__device__ float g_z    [(size_t)BN*CC*SP];
__device__ float g_rdiff[(size_t)BN*CC*SP];
__device__ float g_dz   [(size_t)BN*CC*SP];
__device__ float g_pre  [(size_t)BN*BOT*SP];
__device__ float g_dpre [(size_t)BN*BOT*SP];
__device__ float g_mean [BN*GRP];
__device__ float g_rstd [BN*GRP];
__device__ float g_cm   [CC];
__device__ float g_cv   [CC];
__device__ float g_cnt  [1];
__device__ float g_gst  [BN*GRP*2];
__device__ float g_zst  [CC*2];
__device__ float g_Abk  [BN*HID];
__device__ float g_Bbk  [BN*HID];
__device__ float g_s1   [BN*GRP];
__device__ float g_s2   [BN*GRP];
__device__ float g_gnwf [HID];
__device__ float g_gnbf [HID];
__device__ float g_w1f  [HID*CC];
__device__ float g_w2f  [CC*HID];
__device__ float g_pw1  [(size_t)BN*HID*CC];
__device__ float g_pw2  [(size_t)BN*CC*HID];
__device__ float g_pool [BN*CC];
__device__ float g_gate [BN];
// bf16 big intermediates
__device__ __nv_bfloat16 g_h1b  [(size_t)BN*HID*SP];   // h1 bf16 natural
__device__ __nv_bfloat16 g_dy16 [(size_t)BN*HID*SP];   // dy bf16 natural
// bf16 operands
__device__ __nv_bfloat16 g_bx   [(size_t)BN*SP*CC];
__device__ __nv_bfloat16 g_bxn  [(size_t)BN*CC*SP];
__device__ __nv_bfloat16 g_bact [(size_t)BN*SP*HID];
__device__ __nv_bfloat16 g_bactn[(size_t)BN*HID*SP];
__device__ __nv_bfloat16 g_bzm  [(size_t)BN*SP*CC];
__device__ __nv_bfloat16 g_bgp  [(size_t)BN*SP*BOT];
__device__ __nv_bfloat16 g_brd  [(size_t)BN*SP*CC];
__device__ __nv_bfloat16 g_bdp  [(size_t)BN*SP*BOT];
__device__ __nv_bfloat16 g_bdz  [(size_t)BN*SP*CC];
__device__ __nv_bfloat16 g_bdzn [(size_t)BN*CC*SP];
__device__ __nv_bfloat16 g_bdyn [(size_t)BN*HID*SP];
// bf16 weights
__device__ __nv_bfloat16 g_wb1  [HID*CC];
__device__ __nv_bfloat16 g_wb2  [CC*HID];
__device__ __nv_bfloat16 g_rb1p [128*CC];
__device__ __nv_bfloat16 g_rb2  [CC*BOT];
__device__ __nv_bfloat16 g_rb2tp[128*CC];
__device__ __nv_bfloat16 g_rb1t [CC*BOT];
__device__ __nv_bfloat16 g_wb2t [HID*CC];
__device__ __nv_bfloat16 g_wb1f [HID*CC];
__device__ __nv_bfloat16 g_wb2f [CC*HID];

__device__ __forceinline__ float geluf(float x) {
    return 0.5f * x * (1.0f + erff(x * 0.70710678118654752f));
}
__device__ __forceinline__ float gelugradf(float x) {
    float cdf = 0.5f * (1.0f + erff(x * 0.70710678118654752f));
    float pdf = 0.3989422804014327f * expf(-0.5f * x * x);
    return cdf + x * pdf;
}

__device__ __forceinline__ uint32_t s2u(const void* p) {
    uint32_t a;
    asm("{ .reg .u64 t; cvta.to.shared.u64 t, %1; cvt.u32.u64 %0, t; }" : "=r"(a) : "l"(p));
    return a;
}
__device__ __forceinline__ void ldsm4(uint32_t* r, uint32_t addr) {
    asm volatile("ldmatrix.sync.aligned.m8n8.x4.shared.b16 {%0,%1,%2,%3}, [%4];"
                 : "=r"(r[0]), "=r"(r[1]), "=r"(r[2]), "=r"(r[3]) : "r"(addr));
}
__device__ __forceinline__ void mma16816(float* c, const uint32_t* a, uint32_t b0, uint32_t b1) {
    asm volatile("mma.sync.aligned.m16n8k16.row.col.f32.bf16.bf16.f32 "
                 "{%0,%1,%2,%3}, {%4,%5,%6,%7}, {%8,%9}, {%0,%1,%2,%3};"
                 : "+f"(c[0]), "+f"(c[1]), "+f"(c[2]), "+f"(c[3])
                 : "r"(a[0]), "r"(a[1]), "r"(a[2]), "r"(a[3]), "r"(b0), "r"(b1));
}
__device__ __forceinline__ float qred(float v) {
    v += __shfl_xor_sync(0xFFFFFFFFu, v, 1);
    v += __shfl_xor_sync(0xFFFFFFFFu, v, 2);
    return v;
}
__device__ __forceinline__ float wred(float v) {
    #pragma unroll
    for (int o = 16; o > 0; o >>= 1) v += __shfl_xor_sync(0xFFFFFFFFu, v, o);
    return v;
}
__device__ __forceinline__ float2 bf2f(uint32_t p) {
    __nv_bfloat162 b = *(__nv_bfloat162*)&p;
    return make_float2(__bfloat162float(b.x), __bfloat162float(b.y));
}

enum { EPI_STORE = 0, EPI_ADDX = 1, EPI_RDIFF = 2, EPI_DPRE = 3,
       EPI_DZ = 4, EPI_DY = 5, EPI_FINAL = 6, EPI_NT = 7, EPI_H1 = 8 };

struct EpiArgs {
    const float *x, *z, *rdiff, *pre, *cm, *cv, *cnt, *mean, *rstd, *gnw, *gnb, *gate, *rs;
    const __nv_bfloat16 *h1b;
    float *gst, *abk, *bbk, *zst;
};

#define PITCH 72   // bf16 per smem row (144 B) — conflict-free ldmatrix

// mma.sync GEMM: D[b][m,n] = sum_k A[m,k]*Bt[b][n,k], bf16 in, f32 acc.
// CTA tile 128x128, K chunk 64. 8 warps: 4 over M, 2 over N.
template<int EPI, bool ABATCH, bool OUTBF>
__global__ void __launch_bounds__(256)
mmas(const __nv_bfloat16* __restrict__ A, int lda, size_t aB,
     const __nv_bfloat16* __restrict__ Bt, int ldb, size_t bB,
     float* __restrict__ out, int Mlog, int ldout, size_t outB,
     int nchunks, const int* __restrict__ mask, EpiArgs ea)
{
    __shared__ __align__(16) __nv_bfloat16 As[128 * PITCH];
    __shared__ __align__(16) __nv_bfloat16 Bs[128 * PITCH];

    const int tid = threadIdx.x, wid = tid >> 5, lane = tid & 31;
    const int wm = wid & 3, wn = wid >> 2;
    const int n0 = blockIdx.x * 128, m0 = blockIdx.y * 128, b = blockIdx.z;

    const char* Ab = (const char*)(A + (ABATCH ? (size_t)b * aB : 0));
    const char* Bb = (const char*)(Bt + (size_t)b * bB);
    const uint32_t aU = s2u(As), bU = s2u(Bs);

    float acc[2][8][4];
    #pragma unroll
    for (int i = 0; i < 2; i++)
        #pragma unroll
        for (int j = 0; j < 8; j++)
            #pragma unroll
            for (int k = 0; k < 4; k++) acc[i][j][k] = 0.0f;

    for (int kc = 0; kc < nchunks; kc++) {
        const size_t kof = (size_t)kc * 128;
        #pragma unroll
        for (int i = 0; i < 4; i++) {
            int s_ = tid + i * 256, row = s_ >> 3, seg = s_ & 7;
            *(uint4*)((char*)As + row * (PITCH * 2) + seg * 16) =
                *(const uint4*)(Ab + (size_t)(m0 + row) * lda * 2 + kof + seg * 16);
            *(uint4*)((char*)Bs + row * (PITCH * 2) + seg * 16) =
                *(const uint4*)(Bb + (size_t)(n0 + row) * ldb * 2 + kof + seg * 16);
        }
        __syncthreads();
        #pragma unroll
        for (int kk = 0; kk < 4; kk++) {
            const uint32_t koff = kk * 32 + (lane >> 4) * 16;
            uint32_t af[2][4];
            #pragma unroll
            for (int mi = 0; mi < 2; mi++)
                ldsm4(af[mi], aU + (wm * 32 + mi * 16 + (lane & 15)) * (PITCH * 2) + koff);
            uint32_t bf[4][4];
            #pragma unroll
            for (int nq = 0; nq < 4; nq++)
                ldsm4(bf[nq], bU + (wn * 64 + nq * 16 + (lane & 15)) * (PITCH * 2) + koff);
            #pragma unroll
            for (int mi = 0; mi < 2; mi++)
                #pragma unroll
                for (int nj = 0; nj < 8; nj++) {
                    const int nq = nj >> 1, hi = nj & 1;
                    mma16816(acc[mi][nj], af[mi], bf[nq][hi], bf[nq][2 + hi]);
                }
        }
        __syncthreads();
    }

    const int g = lane >> 2, tg = lane & 3;
    const float sc = (EPI == EPI_DPRE || EPI == EPI_DZ)
                   ? 2.0f / (ea.cnt[0] * 256.0f + 1e-8f) : 0.0f;
    float wsum = 0.f, wssq = 0.f;  // EPI_H1 warp-level stats
    #pragma unroll
    for (int mi = 0; mi < 2; mi++) {
        #pragma unroll
        for (int h = 0; h < 2; h++) {
            const int row = m0 + wm * 32 + mi * 16 + g + h * 8;
            if (row >= Mlog) continue;
            float sdy = 0.f, sdx = 0.f;    // EPI_DY row stats
            float rsum = 0.f, rssq = 0.f;  // EPI_ADDX row stats
            #pragma unroll
            for (int nj = 0; nj < 8; nj++) {
                const int col = n0 + wn * 64 + nj * 8 + tg * 2;
                const size_t gi = (size_t)b * outB + (size_t)row * ldout + col;
                float v0 = acc[mi][nj][h * 2 + 0];
                float v1 = acc[mi][nj][h * 2 + 1];
                if (EPI == EPI_H1) {
                    wsum += v0 + v1; wssq += v0 * v0 + v1 * v1;
                } else if (EPI == EPI_ADDX) {
                    float2 xv = *(const float2*)(ea.x + gi);
                    v0 += xv.x; v1 += xv.y;
                    rsum += v0 + v1; rssq += v0 * v0 + v1 * v1;
                } else if (EPI == EPI_RDIFF) {
                    int2 mk = *(const int2*)(mask + b * SP + col);
                    float2 zv = *(const float2*)(ea.z + gi);
                    v0 = (v0 - zv.x) * (1.0f - (float)mk.x);
                    v1 = (v1 - zv.y) * (1.0f - (float)mk.y);
                } else if (EPI == EPI_DPRE) {
                    float2 pv = *(const float2*)(ea.pre + gi);
                    v0 = v0 * gelugradf(pv.x) * sc;
                    v1 = v1 * gelugradf(pv.y) * sc;
                } else if (EPI == EPI_DZ) {
                    int2 mk = *(const int2*)(mask + b * SP + col);
                    float2 zv = *(const float2*)(ea.z + gi);
                    float2 rv = *(const float2*)(ea.rdiff + gi);
                    float cmc = ea.cm[row];
                    float cvs = ea.cv[row] * (1.0f / (1.0f + 1e-8f));
                    float t1 = 2.0f * cmc * (1.0f / (256.0f * 131072.0f));
                    float t2 = 4.0f * (cvs - 1.0f) * (1.0f / (256.0f * 131071.0f))
                             * (1.0f / (1.0f + 1e-8f));
                    v0 = (float)mk.x * v0 - sc * rv.x + 0.1f * (t1 + t2 * (zv.x - cmc));
                    v1 = (float)mk.y * v1 - sc * rv.y + 0.1f * (t1 + t2 * (zv.y - cmc));
                } else if (EPI == EPI_DY) {
                    int gg = row >> 6;
                    float mn = ea.mean[b * GRP + gg], rsd = ea.rstd[b * GRP + gg];
                    float w = ea.gnw[row], bb = ea.gnb[row];
                    float2 hv = bf2f(*(const uint32_t*)(ea.h1b + gi));
                    float xh0 = (hv.x - mn) * rsd, xh1 = (hv.y - mn) * rsd;
                    v0 *= gelugradf(xh0 * w + bb);
                    v1 *= gelugradf(xh1 * w + bb);
                    sdy += v0 + v1; sdx += v0 * xh0 + v1 * xh1;
                } else if (EPI == EPI_FINAL) {
                    float gt = ea.rs[0] * ea.gate[b];
                    float2 xv = *(const float2*)(ea.x + gi);
                    v0 = xv.x + gt * v0; v1 = xv.y + gt * v1;
                }
                if (OUTBF)
                    *(__nv_bfloat162*)((__nv_bfloat16*)out + gi) = __floats2bfloat162_rn(v0, v1);
                else
                    *(float2*)(out + gi) = make_float2(v0, v1);
            }
            if (EPI == EPI_DY) {
                sdy = qred(sdy); sdx = qred(sdx);
                if (tg == 0) {
                    atomicAdd(ea.abk + b * HID + row, sdy);
                    atomicAdd(ea.bbk + b * HID + row, sdx);
                }
            }
            if (EPI == EPI_ADDX) {
                rsum = qred(rsum); rssq = qred(rssq);
                if (tg == 0) {
                    atomicAdd(ea.zst + row * 2 + 0, rsum);
                    atomicAdd(ea.zst + row * 2 + 1, rssq);
                }
            }
        }
    }
    if (EPI == EPI_H1) {
        wsum = wred(wsum); wssq = wred(wssq);
        if (lane == 0) {
            int idx = b * GRP + (m0 >> 6) + (wm >> 1);
            atomicAdd(ea.gst + idx * 2 + 0, wsum);
            atomicAdd(ea.gst + idx * 2 + 1, wssq);
        }
    }
}

// Transpose+convert [b][C][s] -> bf16 [b][s][C]; OP: 0 none, 1 mask, 2 gelu, 3 GN+gelu.
// SRCBF: source is bf16 (h1b) instead of fp32.
template<int C, int OP, bool DUAL, bool SRCBF>
__global__ void __launch_bounds__(256)
tconv_k(const void* __restrict__ srcv, __nv_bfloat16* __restrict__ dT,
        __nv_bfloat16* __restrict__ dN, const int* __restrict__ mask,
        const float* __restrict__ mean, const float* __restrict__ rstd,
        const float* __restrict__ gnw, const float* __restrict__ gnb)
{
    __shared__ float t[64][65];
    const int tid = threadIdx.x;
    const int b = blockIdx.z, s0 = blockIdx.x * 64, c0 = blockIdx.y * 64;
    const int sc = (tid & 15) * 4, rc = tid >> 4;
    #pragma unroll
    for (int p = 0; p < 4; p++) {
        int cl = rc + 16 * p, c = c0 + cl;
        const size_t off = ((size_t)b * C + c) * SP + s0 + sc;
        float4 v;
        if (SRCBF) {
            uint2 q = *(const uint2*)((const __nv_bfloat16*)srcv + off);
            float2 lo = bf2f(q.x), hi = bf2f(q.y);
            v = make_float4(lo.x, lo.y, hi.x, hi.y);
        } else {
            v = *(const float4*)((const float*)srcv + off);
        }
        if (OP == 1) {
            int4 mk = *(const int4*)(mask + b * SP + s0 + sc);
            v.x *= (float)mk.x; v.y *= (float)mk.y; v.z *= (float)mk.z; v.w *= (float)mk.w;
        } else if (OP == 2) {
            v.x = geluf(v.x); v.y = geluf(v.y); v.z = geluf(v.z); v.w = geluf(v.w);
        } else if (OP == 3) {
            int bg = b * GRP + (c >> 6);
            float m = mean[bg], r = rstd[bg], w = gnw[c], bb = gnb[c];
            v.x = geluf((v.x - m) * r * w + bb); v.y = geluf((v.y - m) * r * w + bb);
            v.z = geluf((v.z - m) * r * w + bb); v.w = geluf((v.w - m) * r * w + bb);
        }
        t[cl][sc] = v.x; t[cl][sc + 1] = v.y; t[cl][sc + 2] = v.z; t[cl][sc + 3] = v.w;
        if (DUAL) {
            __nv_bfloat162 lo = __floats2bfloat162_rn(v.x, v.y);
            __nv_bfloat162 hi = __floats2bfloat162_rn(v.z, v.w);
            uint2 pk; pk.x = *(uint32_t*)&lo; pk.y = *(uint32_t*)&hi;
            *(uint2*)(dN + ((size_t)b * C + c) * SP + s0 + sc) = pk;
        }
    }
    __syncthreads();
    const int cc = (tid & 31) * 2, sr = tid >> 5;
    #pragma unroll
    for (int p = 0; p < 8; p++) {
        int sl = sr + 8 * p;
        __nv_bfloat162 o = __floats2bfloat162_rn(t[cc][sl], t[cc + 1][sl]);
        *(__nv_bfloat162*)(dT + ((size_t)b * SP + s0 + sl) * C + c0 + cc) = o;
    }
}

__global__ void wconv_k(const float* __restrict__ src, __nv_bfloat16* __restrict__ dst,
                        int M, int K, int Msrc, int srs, int T)
{
    int i = blockIdx.x * 256 + threadIdx.x;
    if (i < M * K) {
        int m = i / K, k = i % K;
        float v = 0.0f;
        if (m < Msrc) v = T ? src[(size_t)k * srs + m] : src[(size_t)m * K + k];
        dst[i] = __float2bfloat16_rn(v);
    }
}

__global__ void zero_k(float* __restrict__ p, int n)
{
    int i = blockIdx.x * 256 + threadIdx.x;
    if (i < n) p[i] = 0.0f;
}

__global__ void gnfin_k(const float* __restrict__ gst, float* __restrict__ mean,
                        float* __restrict__ rstd)
{
    int bg = threadIdx.x;   // 256
    float s = gst[bg * 2], ss = gst[bg * 2 + 1];
    float m = s * (1.0f / (GC * SP));
    float var = ss * (1.0f / (GC * SP)) - m * m;
    mean[bg] = m;
    rstd[bg] = rsqrtf(var + 1e-5f);
}

__global__ void zfin_k(const float* __restrict__ zst, float* __restrict__ cm,
                       float* __restrict__ cv)
{
    int c = threadIdx.x;    // 256
    float s = zst[c * 2], ss = zst[c * 2 + 1];
    float m = s * (1.0f / NTOT);
    cm[c] = m;
    cv[c] = (ss - (float)NTOT * m * m) * (1.0f / (NTOT - 1));
}

__global__ void mask_count_k(const int* __restrict__ mask, float* __restrict__ cnt)
{
    int s = 0;
    for (int i = threadIdx.x; i < NTOT; i += 256) s += 1 - mask[i];
    __shared__ int sh[256];
    sh[threadIdx.x] = s;
    __syncthreads();
    for (int o = 128; o > 0; o >>= 1) {
        if (threadIdx.x < o) sh[threadIdx.x] += sh[threadIdx.x + o];
        __syncthreads();
    }
    if (threadIdx.x == 0) cnt[0] = (float)sh[0];
}

__global__ void gn_update_k(const float* __restrict__ Abk, const float* __restrict__ Bbk,
                            const float* __restrict__ gnw, const float* __restrict__ gnb,
                            float* __restrict__ gnwf, float* __restrict__ gnbf)
{
    const int k = threadIdx.x;
    float ga = 0.f, gw = 0.f;
    for (int b = 0; b < BN; b++) { ga += Abk[b * HID + k]; gw += Bbk[b * HID + k]; }
    gnbf[k] = gnb[k] - LRf * ga;
    gnwf[k] = gnw[k] - LRf * gw;
}

__global__ void s12_k(const float* __restrict__ Abk, const float* __restrict__ Bbk,
                      const float* __restrict__ gnw, float* __restrict__ s1,
                      float* __restrict__ s2)
{
    const int bg = threadIdx.x;
    const int b = bg >> 3, g = bg & 7;
    float a = 0.f, c = 0.f;
    for (int l = 0; l < GC; l++) {
        int k = g * GC + l;
        float w = gnw[k];
        a += w * Abk[b * HID + k];
        c += w * Bbk[b * HID + k];
    }
    s1[bg] = a; s2[bg] = c;
}

// GN input-grad from bf16 dy + bf16 h1 -> bf16 natural (NT GEMM operand).
__global__ void dh1_bf_k(const __nv_bfloat16* __restrict__ dy16,
                         const __nv_bfloat16* __restrict__ h1b,
                         const float* __restrict__ mean, const float* __restrict__ rstd,
                         const float* __restrict__ gnw, const float* __restrict__ s1,
                         const float* __restrict__ s2, __nv_bfloat16* __restrict__ outb)
{
    size_t i4 = (size_t)blockIdx.x * 256 + threadIdx.x;
    size_t base = i4 * 4;
    int k  = (int)((base >> 12) & 511);
    int bg = (int)(base >> 18);
    float m = mean[bg], r = rstd[bg], w = gnw[k];
    const float invM = 1.0f / (GC * SP);
    float a = s1[bg] * invM, c = s2[bg] * invM;
    uint2 qd = *(const uint2*)(dy16 + base);
    uint2 qh = *(const uint2*)(h1b + base);
    float2 d01 = bf2f(qd.x), d23 = bf2f(qd.y);
    float2 h01 = bf2f(qh.x), h23 = bf2f(qh.y);
    float o0 = r * (w * d01.x - a - (h01.x - m) * r * c);
    float o1 = r * (w * d01.y - a - (h01.y - m) * r * c);
    float o2 = r * (w * d23.x - a - (h23.x - m) * r * c);
    float o3 = r * (w * d23.y - a - (h23.y - m) * r * c);
    __nv_bfloat162 lo = __floats2bfloat162_rn(o0, o1);
    __nv_bfloat162 hi = __floats2bfloat162_rn(o2, o3);
    uint2 pk; pk.x = *(uint32_t*)&lo; pk.y = *(uint32_t*)&hi;
    *(uint2*)(outb + base) = pk;
}

__global__ void reduce_update_k(const float* __restrict__ P, const float* __restrict__ w,
                                float* __restrict__ wf, int MN)
{
    int i = blockIdx.x * 256 + threadIdx.x;
    if (i < MN) {
        float s = 0.f;
        for (int b = 0; b < BN; b++) s += P[(size_t)b * MN + i];
        wf[i] = w[i] - LRf * s;
    }
}

__global__ void pooled_k(const float* __restrict__ x, float* __restrict__ pooled)
{
    const int bc = blockIdx.x;
    const float* p = x + (size_t)bc * SP;
    float s = 0.f;
    for (int i = threadIdx.x; i < SP; i += 128) s += p[i];
    __shared__ float sh[128];
    sh[threadIdx.x] = s;
    __syncthreads();
    for (int o = 64; o > 0; o >>= 1) {
        if (threadIdx.x < o) sh[threadIdx.x] += sh[threadIdx.x + o];
        __syncthreads();
    }
    if (threadIdx.x == 0) pooled[bc] = sh[0] * (1.0f / SP);
}

__global__ void gate_k(const float* __restrict__ pooled, const float* __restrict__ gw1,
                       const float* __restrict__ gb1, const float* __restrict__ gw2,
                       const float* __restrict__ gb2, float* __restrict__ gate)
{
    const int b = blockIdx.x, j = threadIdx.x;
    float acc = gb1[j];
    for (int c = 0; c < CC; c++) acc += pooled[b * CC + c] * gw1[j * CC + c];
    __shared__ float sh[64];
    sh[j] = geluf(acc) * gw2[j];
    __syncthreads();
    for (int o = 32; o > 0; o >>= 1) {
        if (j < o) sh[j] += sh[j + o];
        __syncthreads();
    }
    if (j == 0) gate[b] = 1.0f / (1.0f + expf(-(sh[0] + gb2[0])));
}

#define GSA(v, s) cudaGetSymbolAddress((void**)&v, s)

extern "C" void kernel_launch(void* const* d_in, const int* in_sizes, int n_in,
                              void* d_out, int out_size)
{
    const float* x    = (const float*)d_in[0];
    const int*   mask = (const int*)  d_in[1];
    const float* w1   = (const float*)d_in[2];
    const float* gnw  = (const float*)d_in[3];
    const float* gnb  = (const float*)d_in[4];
    const float* w2   = (const float*)d_in[5];
    const float* rc1  = (const float*)d_in[6];
    const float* rc2  = (const float*)d_in[7];
    const float* gw1  = (const float*)d_in[8];
    const float* gb1  = (const float*)d_in[9];
    const float* gw2  = (const float*)d_in[10];
    const float* gb2  = (const float*)d_in[11];
    const float* rs   = (const float*)d_in[12];
    float* out = (float*)d_out;
    (void)in_sizes; (void)n_in; (void)out_size;

    float *z, *rdiff, *dz, *pre, *dpre, *meanb, *rstdb, *cm, *cv, *cnt, *gst, *zst;
    float *Abk, *Bbk, *s1, *s2, *gnwf, *gnbf, *w1f, *w2f, *pw1, *pw2, *pooled, *gate;
    __nv_bfloat16 *h1b, *dy16;
    __nv_bfloat16 *bx, *bxn, *bact, *bactn, *bzm, *bgp, *brd, *bdp, *bdz, *bdzn, *bdyn;
    __nv_bfloat16 *wb1, *wb2, *rb1p, *rb2, *rb2tp, *rb1t, *wb2t, *wb1f, *wb2f;
    GSA(z, g_z); GSA(rdiff, g_rdiff); GSA(dz, g_dz);
    GSA(pre, g_pre); GSA(dpre, g_dpre); GSA(meanb, g_mean); GSA(rstdb, g_rstd);
    GSA(cm, g_cm); GSA(cv, g_cv); GSA(cnt, g_cnt); GSA(gst, g_gst); GSA(zst, g_zst);
    GSA(Abk, g_Abk); GSA(Bbk, g_Bbk);
    GSA(s1, g_s1); GSA(s2, g_s2); GSA(gnwf, g_gnwf); GSA(gnbf, g_gnbf);
    GSA(w1f, g_w1f); GSA(w2f, g_w2f); GSA(pw1, g_pw1); GSA(pw2, g_pw2);
    GSA(pooled, g_pool); GSA(gate, g_gate);
    GSA(h1b, g_h1b); GSA(dy16, g_dy16);
    GSA(bx, g_bx); GSA(bxn, g_bxn); GSA(bact, g_bact); GSA(bactn, g_bactn);
    GSA(bzm, g_bzm); GSA(bgp, g_bgp); GSA(brd, g_brd); GSA(bdp, g_bdp);
    GSA(bdz, g_bdz); GSA(bdzn, g_bdzn); GSA(bdyn, g_bdyn);
    GSA(wb1, g_wb1); GSA(wb2, g_wb2); GSA(rb1p, g_rb1p); GSA(rb2, g_rb2);
    GSA(rb2tp, g_rb2tp); GSA(rb1t, g_rb1t); GSA(wb2t, g_wb2t);
    GSA(wb1f, g_wb1f); GSA(wb2f, g_wb2f);

    // independent small work + accumulator zeroing
    pooled_k<<<BN * CC, 128>>>(x, pooled);
    gate_k<<<BN, 64>>>(pooled, gw1, gb1, gw2, gb2, gate);
    mask_count_k<<<1, 256>>>(mask, cnt);
    zero_k<<<2, 256>>>(gst, BN * GRP * 2);
    zero_k<<<2, 256>>>(zst, CC * 2);
    zero_k<<<64, 256>>>(Abk, BN * HID);
    zero_k<<<64, 256>>>(Bbk, BN * HID);

    // weight conversions
    wconv_k<<<512, 256>>>(w1,  wb1,  HID, CC, HID, 0, 0);
    wconv_k<<<512, 256>>>(w2,  wb2,  CC, HID, CC, 0, 0);
    wconv_k<<<128, 256>>>(rc1, rb1p, 128, CC, BOT, 0, 0);
    wconv_k<<<64,  256>>>(rc2, rb2,  CC, BOT, CC, 0, 0);
    wconv_k<<<128, 256>>>(rc2, rb2tp, 128, CC, BOT, BOT, 1);
    wconv_k<<<64,  256>>>(rc1, rb1t, CC, BOT, CC, CC, 1);
    wconv_k<<<512, 256>>>(w2,  wb2t, HID, CC, HID, HID, 1);

    // x -> bf16 (T + natural)
    tconv_k<CC, 0, true, false><<<dim3(64, 4, BN), 256>>>(x, bx, bxn, mask, 0, 0, 0, 0);

    EpiArgs ez = {};
    // h1 = w1 . x  -> bf16 + fused GN stats
    { EpiArgs ea = ez; ea.gst = gst;
      mmas<EPI_H1, false, true><<<dim3(32, 4, BN), 256>>>(wb1, CC, 0, bx, CC, (size_t)SP * CC,
          (float*)h1b, HID, SP, (size_t)HID * SP, 4, mask, ea); }
    gnfin_k<<<1, BN * GRP>>>(gst, meanb, rstdb);
    // act = gelu(GN(h1)) -> bf16 T + natural
    tconv_k<HID, 3, true, true><<<dim3(64, 8, BN), 256>>>(h1b, bact, bactn, mask,
        meanb, rstdb, gnw, gnb);
    // z = w2 . act + x  (+ fused z stats)
    { EpiArgs ea = ez; ea.x = x; ea.zst = zst;
      mmas<EPI_ADDX, false, false><<<dim3(32, 2, BN), 256>>>(wb2, HID, 0, bact, HID,
          (size_t)SP * HID, z, CC, SP, (size_t)CC * SP, 8, mask, ea); }
    zfin_k<<<1, CC>>>(zst, cm, cv);
    // pre = rc1 . (z*mask)
    tconv_k<CC, 1, false, false><<<dim3(64, 4, BN), 256>>>(z, bzm, 0, mask, 0, 0, 0, 0);
    mmas<EPI_STORE, false, false><<<dim3(32, 1, BN), 256>>>(rb1p, CC, 0, bzm, CC,
        (size_t)SP * CC, pre, BOT, SP, (size_t)BOT * SP, 4, mask, ez);
    // rdiff = (rc2 . gelu(pre) - z) * inv
    tconv_k<BOT, 2, false, false><<<dim3(64, 1, BN), 256>>>(pre, bgp, 0, mask, 0, 0, 0, 0);
    { EpiArgs ea = ez; ea.z = z;
      mmas<EPI_RDIFF, false, false><<<dim3(32, 2, BN), 256>>>(rb2, BOT, 0, bgp, BOT,
          (size_t)SP * BOT, rdiff, CC, SP, (size_t)CC * SP, 1, mask, ea); }
    // dpre = (rc2^T . rdiff) * g'(pre) * sc
    tconv_k<CC, 0, false, false><<<dim3(64, 4, BN), 256>>>(rdiff, brd, 0, mask, 0, 0, 0, 0);
    { EpiArgs ea = ez; ea.pre = pre; ea.cnt = cnt;
      mmas<EPI_DPRE, false, false><<<dim3(32, 1, BN), 256>>>(rb2tp, CC, 0, brd, CC,
          (size_t)SP * CC, dpre, BOT, SP, (size_t)BOT * SP, 4, mask, ea); }
    // dz = mask*(rc1^T . dpre) - sc*rdiff + consist
    tconv_k<BOT, 0, false, false><<<dim3(64, 1, BN), 256>>>(dpre, bdp, 0, mask, 0, 0, 0, 0);
    { EpiArgs ea = ez; ea.rdiff = rdiff; ea.z = z; ea.cm = cm; ea.cv = cv; ea.cnt = cnt;
      mmas<EPI_DZ, false, false><<<dim3(32, 2, BN), 256>>>(rb1t, BOT, 0, bdp, BOT,
          (size_t)SP * BOT, dz, CC, SP, (size_t)CC * SP, 1, mask, ea); }
    tconv_k<CC, 0, true, false><<<dim3(64, 4, BN), 256>>>(dz, bdz, bdzn, mask, 0, 0, 0, 0);
    // dy = (w2^T . dz) * g'(GN(h1))  -> bf16 + fused bkpart atomics
    { EpiArgs ea = ez; ea.h1b = h1b; ea.mean = meanb; ea.rstd = rstdb;
      ea.gnw = gnw; ea.gnb = gnb; ea.abk = Abk; ea.bbk = Bbk;
      mmas<EPI_DY, false, true><<<dim3(32, 4, BN), 256>>>(wb2t, CC, 0, bdz, CC,
          (size_t)SP * CC, (float*)dy16, HID, SP, (size_t)HID * SP, 4, mask, ea); }
    gn_update_k<<<1, HID>>>(Abk, Bbk, gnw, gnb, gnwf, gnbf);
    s12_k<<<1, BN * GRP>>>(Abk, Bbk, gnw, s1, s2);
    dh1_bf_k<<<65536, 256>>>(dy16, h1b, meanb, rstdb, gnw, s1, s2, bdyn);
    // grad_w1 = dh1 . x^T (split-K over batch, reduce after)
    mmas<EPI_NT, true, false><<<dim3(2, 4, BN), 256>>>(bdyn, SP, (size_t)HID * SP, bxn, SP,
        (size_t)CC * SP, pw1, HID, CC, (size_t)HID * CC, 64, mask, ez);
    reduce_update_k<<<512, 256>>>(pw1, w1, w1f, HID * CC);
    // grad_w2 = dz . act^T
    mmas<EPI_NT, true, false><<<dim3(4, 2, BN), 256>>>(bdzn, SP, (size_t)CC * SP, bactn, SP,
        (size_t)HID * SP, pw2, CC, HID, (size_t)CC * HID, 64, mask, ez);
    reduce_update_k<<<512, 256>>>(pw2, w2, w2f, CC * HID);
    wconv_k<<<512, 256>>>(w1f, wb1f, HID, CC, HID, 0, 0);
    wconv_k<<<512, 256>>>(w2f, wb2f, CC, HID, CC, 0, 0);

    // final modifier at fast weights
    zero_k<<<2, 256>>>(gst, BN * GRP * 2);
    { EpiArgs ea = ez; ea.gst = gst;
      mmas<EPI_H1, false, true><<<dim3(32, 4, BN), 256>>>(wb1f, CC, 0, bx, CC,
          (size_t)SP * CC, (float*)h1b, HID, SP, (size_t)HID * SP, 4, mask, ea); }
    gnfin_k<<<1, BN * GRP>>>(gst, meanb, rstdb);
    tconv_k<HID, 3, false, true><<<dim3(64, 8, BN), 256>>>(h1b, bact, 0, mask,
        meanb, rstdb, gnwf, gnbf);
    { EpiArgs ea = ez; ea.x = x; ea.gate = gate; ea.rs = rs;
      mmas<EPI_FINAL, false, false><<<dim3(32, 2, BN), 256>>>(wb2f, HID, 0, bact, HID,
          (size_t)SP * HID, out, CC, SP, (size_t)CC * SP, 8, mask, ea); }
}

// round 17
// speedup vs baseline: 4.6817x; 1.0567x over previous
#include <cuda_runtime.h>
#include <cuda_bf16.h>
#include <math.h>
#include <stdint.h>

#define BN   32
#define CC   256
#define HID  512
#define SP   4096
#define GRP  8
#define GC   64
#define BOT  64
#define NTOT (BN*SP)
#define LRf  0.005f

// fp32 scratch
__device__ float g_z    [(size_t)BN*CC*SP];
__device__ float g_mean [BN*GRP];
__device__ float g_rstd [BN*GRP];
__device__ float g_cm   [CC];
__device__ float g_cv   [CC];
__device__ float g_cnt  [1];
__device__ float g_gst  [BN*GRP*2];
__device__ float g_zst  [CC*2];
__device__ float g_Abk  [BN*HID];
__device__ float g_Bbk  [BN*HID];
__device__ float g_s1   [BN*GRP];
__device__ float g_s2   [BN*GRP];
__device__ float g_gnwf [HID];
__device__ float g_gnbf [HID];
__device__ float g_w1f  [HID*CC];
__device__ float g_w2f  [CC*HID];
__device__ float g_pw1  [(size_t)BN*HID*CC];
__device__ float g_pw2  [(size_t)BN*CC*HID];
__device__ float g_pool [BN*CC];
__device__ float g_gate [BN];
// bf16 big intermediates
__device__ __nv_bfloat16 g_h1b  [(size_t)BN*HID*SP];
__device__ __nv_bfloat16 g_dy16 [(size_t)BN*HID*SP];
__device__ __nv_bfloat16 g_rd16 [(size_t)BN*CC*SP];    // rdiff bf16 natural
__device__ __nv_bfloat16 g_pre16[(size_t)BN*BOT*SP];   // pre bf16 natural
__device__ __nv_bfloat16 g_dp16 [(size_t)BN*BOT*SP];   // dpre bf16 natural
// bf16 operands
__device__ __nv_bfloat16 g_bx   [(size_t)BN*SP*CC];
__device__ __nv_bfloat16 g_bxn  [(size_t)BN*CC*SP];
__device__ __nv_bfloat16 g_bact [(size_t)BN*SP*HID];
__device__ __nv_bfloat16 g_bactn[(size_t)BN*HID*SP];
__device__ __nv_bfloat16 g_bzm  [(size_t)BN*SP*CC];
__device__ __nv_bfloat16 g_bgp  [(size_t)BN*SP*BOT];
__device__ __nv_bfloat16 g_brd  [(size_t)BN*SP*CC];
__device__ __nv_bfloat16 g_bdp  [(size_t)BN*SP*BOT];
__device__ __nv_bfloat16 g_bdz  [(size_t)BN*SP*CC];
__device__ __nv_bfloat16 g_bdzn [(size_t)BN*CC*SP];
__device__ __nv_bfloat16 g_bdyn [(size_t)BN*HID*SP];
// bf16 weights
__device__ __nv_bfloat16 g_wb1  [HID*CC];
__device__ __nv_bfloat16 g_wb2  [CC*HID];
__device__ __nv_bfloat16 g_rb1p [128*CC];
__device__ __nv_bfloat16 g_rb2  [CC*BOT];
__device__ __nv_bfloat16 g_rb2tp[128*CC];
__device__ __nv_bfloat16 g_rb1t [CC*BOT];
__device__ __nv_bfloat16 g_wb2t [HID*CC];
__device__ __nv_bfloat16 g_wb1f [HID*CC];
__device__ __nv_bfloat16 g_wb2f [CC*HID];

__device__ __forceinline__ float geluf(float x) {
    return 0.5f * x * (1.0f + erff(x * 0.70710678118654752f));
}
__device__ __forceinline__ float gelugradf(float x) {
    float cdf = 0.5f * (1.0f + erff(x * 0.70710678118654752f));
    float pdf = 0.3989422804014327f * expf(-0.5f * x * x);
    return cdf + x * pdf;
}

__device__ __forceinline__ uint32_t s2u(const void* p) {
    uint32_t a;
    asm("{ .reg .u64 t; cvta.to.shared.u64 t, %1; cvt.u32.u64 %0, t; }" : "=r"(a) : "l"(p));
    return a;
}
__device__ __forceinline__ void ldsm4(uint32_t* r, uint32_t addr) {
    asm volatile("ldmatrix.sync.aligned.m8n8.x4.shared.b16 {%0,%1,%2,%3}, [%4];"
                 : "=r"(r[0]), "=r"(r[1]), "=r"(r[2]), "=r"(r[3]) : "r"(addr));
}
__device__ __forceinline__ void mma16816(float* c, const uint32_t* a, uint32_t b0, uint32_t b1) {
    asm volatile("mma.sync.aligned.m16n8k16.row.col.f32.bf16.bf16.f32 "
                 "{%0,%1,%2,%3}, {%4,%5,%6,%7}, {%8,%9}, {%0,%1,%2,%3};"
                 : "+f"(c[0]), "+f"(c[1]), "+f"(c[2]), "+f"(c[3])
                 : "r"(a[0]), "r"(a[1]), "r"(a[2]), "r"(a[3]), "r"(b0), "r"(b1));
}
__device__ __forceinline__ void cpa16(uint32_t d, const void* s) {
    asm volatile("cp.async.cg.shared.global [%0], [%1], 16;" :: "r"(d), "l"(s));
}
__device__ __forceinline__ float qred(float v) {
    v += __shfl_xor_sync(0xFFFFFFFFu, v, 1);
    v += __shfl_xor_sync(0xFFFFFFFFu, v, 2);
    return v;
}
__device__ __forceinline__ float wred(float v) {
    #pragma unroll
    for (int o = 16; o > 0; o >>= 1) v += __shfl_xor_sync(0xFFFFFFFFu, v, o);
    return v;
}
__device__ __forceinline__ float2 bf2f(uint32_t p) {
    __nv_bfloat162 b = *(__nv_bfloat162*)&p;
    return make_float2(__bfloat162float(b.x), __bfloat162float(b.y));
}

enum { EPI_STORE = 0, EPI_ADDX = 1, EPI_RDIFF = 2, EPI_DPRE = 3,
       EPI_DZ = 4, EPI_DY = 5, EPI_FINAL = 6, EPI_NT = 7, EPI_H1 = 8 };

struct EpiArgs {
    const float *x, *z, *cm, *cv, *cnt, *mean, *rstd, *gnw, *gnb, *gate, *rs;
    const __nv_bfloat16 *h1b, *rd16, *pre16;
    float *gst, *abk, *bbk, *zst;
};

#define PITCH 40    // bf16 per smem row (80 B) — conflict-free ldmatrix
#define KCH   32    // K per chunk (bf16) -> 64 B per row per stage
#define STG   10240 // stage stride bytes = 128*PITCH*2

// mma.sync GEMM with cp.async 2-stage pipeline.
// D[b][m,n] = sum_k A[m,k]*Bt[b][n,k], bf16 in, f32 acc. CTA tile 128x128, K chunk 32.
template<int EPI, bool ABATCH, bool OUTBF>
__global__ void __launch_bounds__(256)
mmas(const __nv_bfloat16* __restrict__ A, int lda, size_t aB,
     const __nv_bfloat16* __restrict__ Bt, int ldb, size_t bB,
     float* __restrict__ out, int Mlog, int ldout, size_t outB,
     int nchunks, const int* __restrict__ mask, EpiArgs ea)
{
    __shared__ __align__(16) __nv_bfloat16 As[2][128 * PITCH];
    __shared__ __align__(16) __nv_bfloat16 Bs[2][128 * PITCH];

    const int tid = threadIdx.x, wid = tid >> 5, lane = tid & 31;
    const int wm = wid & 3, wn = wid >> 2;
    const int n0 = blockIdx.x * 128, m0 = blockIdx.y * 128, b = blockIdx.z;

    const char* Ab = (const char*)(A + (ABATCH ? (size_t)b * aB : 0));
    const char* Bb = (const char*)(Bt + (size_t)b * bB);
    const uint32_t aU = s2u(As), bU = s2u(Bs);

    float acc[2][8][4];
    #pragma unroll
    for (int i = 0; i < 2; i++)
        #pragma unroll
        for (int j = 0; j < 8; j++)
            #pragma unroll
            for (int k = 0; k < 4; k++) acc[i][j][k] = 0.0f;

    auto issue = [&](int kc, int st) {
        const size_t kof = (size_t)kc * (KCH * 2);
        const uint32_t ao = aU + st * STG, bo = bU + st * STG;
        #pragma unroll
        for (int i = 0; i < 2; i++) {
            int s_ = tid + i * 256, row = s_ >> 2, seg = s_ & 3;
            cpa16(ao + row * (PITCH * 2) + seg * 16,
                  Ab + (size_t)(m0 + row) * lda * 2 + kof + seg * 16);
            cpa16(bo + row * (PITCH * 2) + seg * 16,
                  Bb + (size_t)(n0 + row) * ldb * 2 + kof + seg * 16);
        }
        asm volatile("cp.async.commit_group;" ::: "memory");
    };

    issue(0, 0);
    for (int kc = 0; kc < nchunks; kc++) {
        const int st = kc & 1;
        if (kc + 1 < nchunks) {
            issue(kc + 1, st ^ 1);
            asm volatile("cp.async.wait_group 1;" ::: "memory");
        } else {
            asm volatile("cp.async.wait_group 0;" ::: "memory");
        }
        __syncthreads();
        const uint32_t aS = aU + st * STG, bS = bU + st * STG;
        #pragma unroll
        for (int kk = 0; kk < 2; kk++) {
            const uint32_t koff = kk * 32 + (lane >> 4) * 16;
            uint32_t af[2][4];
            #pragma unroll
            for (int mi = 0; mi < 2; mi++)
                ldsm4(af[mi], aS + (wm * 32 + mi * 16 + (lane & 15)) * (PITCH * 2) + koff);
            uint32_t bf[4][4];
            #pragma unroll
            for (int nq = 0; nq < 4; nq++)
                ldsm4(bf[nq], bS + (wn * 64 + nq * 16 + (lane & 15)) * (PITCH * 2) + koff);
            #pragma unroll
            for (int mi = 0; mi < 2; mi++)
                #pragma unroll
                for (int nj = 0; nj < 8; nj++) {
                    const int nq = nj >> 1, hi = nj & 1;
                    mma16816(acc[mi][nj], af[mi], bf[nq][hi], bf[nq][2 + hi]);
                }
        }
        __syncthreads();
    }

    const int g = lane >> 2, tg = lane & 3;
    const float sc = (EPI == EPI_DPRE || EPI == EPI_DZ)
                   ? 2.0f / (ea.cnt[0] * 256.0f + 1e-8f) : 0.0f;
    float wsum = 0.f, wssq = 0.f;
    #pragma unroll
    for (int mi = 0; mi < 2; mi++) {
        #pragma unroll
        for (int h = 0; h < 2; h++) {
            const int row = m0 + wm * 32 + mi * 16 + g + h * 8;
            if (row >= Mlog) continue;
            float sdy = 0.f, sdx = 0.f;
            float rsum = 0.f, rssq = 0.f;
            #pragma unroll
            for (int nj = 0; nj < 8; nj++) {
                const int col = n0 + wn * 64 + nj * 8 + tg * 2;
                const size_t gi = (size_t)b * outB + (size_t)row * ldout + col;
                float v0 = acc[mi][nj][h * 2 + 0];
                float v1 = acc[mi][nj][h * 2 + 1];
                if (EPI == EPI_H1) {
                    wsum += v0 + v1; wssq += v0 * v0 + v1 * v1;
                } else if (EPI == EPI_ADDX) {
                    float2 xv = *(const float2*)(ea.x + gi);
                    v0 += xv.x; v1 += xv.y;
                    rsum += v0 + v1; rssq += v0 * v0 + v1 * v1;
                } else if (EPI == EPI_RDIFF) {
                    int2 mk = *(const int2*)(mask + b * SP + col);
                    float2 zv = *(const float2*)(ea.z + gi);
                    v0 = (v0 - zv.x) * (1.0f - (float)mk.x);
                    v1 = (v1 - zv.y) * (1.0f - (float)mk.y);
                } else if (EPI == EPI_DPRE) {
                    float2 pv = bf2f(*(const uint32_t*)(ea.pre16 + gi));
                    v0 = v0 * gelugradf(pv.x) * sc;
                    v1 = v1 * gelugradf(pv.y) * sc;
                } else if (EPI == EPI_DZ) {
                    int2 mk = *(const int2*)(mask + b * SP + col);
                    float2 zv = *(const float2*)(ea.z + gi);
                    float2 rv = bf2f(*(const uint32_t*)(ea.rd16 + gi));
                    float cmc = ea.cm[row];
                    float cvs = ea.cv[row] * (1.0f / (1.0f + 1e-8f));
                    float t1 = 2.0f * cmc * (1.0f / (256.0f * 131072.0f));
                    float t2 = 4.0f * (cvs - 1.0f) * (1.0f / (256.0f * 131071.0f))
                             * (1.0f / (1.0f + 1e-8f));
                    v0 = (float)mk.x * v0 - sc * rv.x + 0.1f * (t1 + t2 * (zv.x - cmc));
                    v1 = (float)mk.y * v1 - sc * rv.y + 0.1f * (t1 + t2 * (zv.y - cmc));
                } else if (EPI == EPI_DY) {
                    int gg = row >> 6;
                    float mn = ea.mean[b * GRP + gg], rsd = ea.rstd[b * GRP + gg];
                    float w = ea.gnw[row], bb = ea.gnb[row];
                    float2 hv = bf2f(*(const uint32_t*)(ea.h1b + gi));
                    float xh0 = (hv.x - mn) * rsd, xh1 = (hv.y - mn) * rsd;
                    v0 *= gelugradf(xh0 * w + bb);
                    v1 *= gelugradf(xh1 * w + bb);
                    sdy += v0 + v1; sdx += v0 * xh0 + v1 * xh1;
                } else if (EPI == EPI_FINAL) {
                    float gt = ea.rs[0] * ea.gate[b];
                    float2 xv = *(const float2*)(ea.x + gi);
                    v0 = xv.x + gt * v0; v1 = xv.y + gt * v1;
                }
                if (OUTBF)
                    *(__nv_bfloat162*)((__nv_bfloat16*)out + gi) = __floats2bfloat162_rn(v0, v1);
                else
                    *(float2*)(out + gi) = make_float2(v0, v1);
            }
            if (EPI == EPI_DY) {
                sdy = qred(sdy); sdx = qred(sdx);
                if (tg == 0) {
                    atomicAdd(ea.abk + b * HID + row, sdy);
                    atomicAdd(ea.bbk + b * HID + row, sdx);
                }
            }
            if (EPI == EPI_ADDX) {
                rsum = qred(rsum); rssq = qred(rssq);
                if (tg == 0) {
                    atomicAdd(ea.zst + row * 2 + 0, rsum);
                    atomicAdd(ea.zst + row * 2 + 1, rssq);
                }
            }
        }
    }
    if (EPI == EPI_H1) {
        wsum = wred(wsum); wssq = wred(wssq);
        if (lane == 0) {
            int idx = b * GRP + (m0 >> 6) + (wm >> 1);
            atomicAdd(ea.gst + idx * 2 + 0, wsum);
            atomicAdd(ea.gst + idx * 2 + 1, wssq);
        }
    }
}

// Transpose+convert [b][C][s] -> bf16 [b][s][C]; OP: 0 none, 1 mask, 2 gelu, 3 GN+gelu.
// SRCBF: bf16 source. POOL: fused per-(b,c) spatial-sum atomics (x pooling).
template<int C, int OP, bool DUAL, bool SRCBF, bool POOL>
__global__ void __launch_bounds__(256)
tconv_k(const void* __restrict__ srcv, __nv_bfloat16* __restrict__ dT,
        __nv_bfloat16* __restrict__ dN, const int* __restrict__ mask,
        const float* __restrict__ mean, const float* __restrict__ rstd,
        const float* __restrict__ gnw, const float* __restrict__ gnb,
        float* __restrict__ pool)
{
    __shared__ float t[64][65];
    const int tid = threadIdx.x;
    const int b = blockIdx.z, s0 = blockIdx.x * 64, c0 = blockIdx.y * 64;
    const int sc = (tid & 15) * 4, rc = tid >> 4;
    #pragma unroll
    for (int p = 0; p < 4; p++) {
        int cl = rc + 16 * p, c = c0 + cl;
        const size_t off = ((size_t)b * C + c) * SP + s0 + sc;
        float4 v;
        if (SRCBF) {
            uint2 q = *(const uint2*)((const __nv_bfloat16*)srcv + off);
            float2 lo = bf2f(q.x), hi = bf2f(q.y);
            v = make_float4(lo.x, lo.y, hi.x, hi.y);
        } else {
            v = *(const float4*)((const float*)srcv + off);
        }
        if (OP == 1) {
            int4 mk = *(const int4*)(mask + b * SP + s0 + sc);
            v.x *= (float)mk.x; v.y *= (float)mk.y; v.z *= (float)mk.z; v.w *= (float)mk.w;
        } else if (OP == 2) {
            v.x = geluf(v.x); v.y = geluf(v.y); v.z = geluf(v.z); v.w = geluf(v.w);
        } else if (OP == 3) {
            int bg = b * GRP + (c >> 6);
            float m = mean[bg], r = rstd[bg], w = gnw[c], bb = gnb[c];
            v.x = geluf((v.x - m) * r * w + bb); v.y = geluf((v.y - m) * r * w + bb);
            v.z = geluf((v.z - m) * r * w + bb); v.w = geluf((v.w - m) * r * w + bb);
        }
        t[cl][sc] = v.x; t[cl][sc + 1] = v.y; t[cl][sc + 2] = v.z; t[cl][sc + 3] = v.w;
        if (DUAL) {
            __nv_bfloat162 lo = __floats2bfloat162_rn(v.x, v.y);
            __nv_bfloat162 hi = __floats2bfloat162_rn(v.z, v.w);
            uint2 pk; pk.x = *(uint32_t*)&lo; pk.y = *(uint32_t*)&hi;
            *(uint2*)(dN + ((size_t)b * C + c) * SP + s0 + sc) = pk;
        }
    }
    __syncthreads();
    if (POOL) {
        if (tid < 64) {
            float s = 0.f;
            #pragma unroll 16
            for (int i = 0; i < 64; i++) s += t[tid][i];
            atomicAdd(pool + b * C + c0 + tid, s);
        }
    }
    const int cc = (tid & 31) * 2, sr = tid >> 5;
    #pragma unroll
    for (int p = 0; p < 8; p++) {
        int sl = sr + 8 * p;
        __nv_bfloat162 o = __floats2bfloat162_rn(t[cc][sl], t[cc + 1][sl]);
        *(__nv_bfloat162*)(dT + ((size_t)b * SP + s0 + sl) * C + c0 + cc) = o;
    }
}

__global__ void wconv_k(const float* __restrict__ src, __nv_bfloat16* __restrict__ dst,
                        int M, int K, int Msrc, int srs, int T)
{
    int i = blockIdx.x * 256 + threadIdx.x;
    if (i < M * K) {
        int m = i / K, k = i % K;
        float v = 0.0f;
        if (m < Msrc) v = T ? src[(size_t)k * srs + m] : src[(size_t)m * K + k];
        dst[i] = __float2bfloat16_rn(v);
    }
}

__global__ void zero_k(float* __restrict__ p, int n)
{
    int i = blockIdx.x * 256 + threadIdx.x;
    if (i < n) p[i] = 0.0f;
}

__global__ void gnfin_k(const float* __restrict__ gst, float* __restrict__ mean,
                        float* __restrict__ rstd)
{
    int bg = threadIdx.x;
    float s = gst[bg * 2], ss = gst[bg * 2 + 1];
    float m = s * (1.0f / (GC * SP));
    float var = ss * (1.0f / (GC * SP)) - m * m;
    mean[bg] = m;
    rstd[bg] = rsqrtf(var + 1e-5f);
}

__global__ void zfin_k(const float* __restrict__ zst, float* __restrict__ cm,
                       float* __restrict__ cv)
{
    int c = threadIdx.x;
    float s = zst[c * 2], ss = zst[c * 2 + 1];
    float m = s * (1.0f / NTOT);
    cm[c] = m;
    cv[c] = (ss - (float)NTOT * m * m) * (1.0f / (NTOT - 1));
}

__global__ void mask_count_k(const int* __restrict__ mask, float* __restrict__ cnt)
{
    int s = 0;
    for (int i = threadIdx.x; i < NTOT; i += 256) s += 1 - mask[i];
    __shared__ int sh[256];
    sh[threadIdx.x] = s;
    __syncthreads();
    for (int o = 128; o > 0; o >>= 1) {
        if (threadIdx.x < o) sh[threadIdx.x] += sh[threadIdx.x + o];
        __syncthreads();
    }
    if (threadIdx.x == 0) cnt[0] = (float)sh[0];
}

__global__ void gn_update_k(const float* __restrict__ Abk, const float* __restrict__ Bbk,
                            const float* __restrict__ gnw, const float* __restrict__ gnb,
                            float* __restrict__ gnwf, float* __restrict__ gnbf)
{
    const int k = threadIdx.x;
    float ga = 0.f, gw = 0.f;
    for (int b = 0; b < BN; b++) { ga += Abk[b * HID + k]; gw += Bbk[b * HID + k]; }
    gnbf[k] = gnb[k] - LRf * ga;
    gnwf[k] = gnw[k] - LRf * gw;
}

__global__ void s12_k(const float* __restrict__ Abk, const float* __restrict__ Bbk,
                      const float* __restrict__ gnw, float* __restrict__ s1,
                      float* __restrict__ s2)
{
    const int bg = threadIdx.x;
    const int b = bg >> 3, g = bg & 7;
    float a = 0.f, c = 0.f;
    for (int l = 0; l < GC; l++) {
        int k = g * GC + l;
        float w = gnw[k];
        a += w * Abk[b * HID + k];
        c += w * Bbk[b * HID + k];
    }
    s1[bg] = a; s2[bg] = c;
}

__global__ void dh1_bf_k(const __nv_bfloat16* __restrict__ dy16,
                         const __nv_bfloat16* __restrict__ h1b,
                         const float* __restrict__ mean, const float* __restrict__ rstd,
                         const float* __restrict__ gnw, const float* __restrict__ s1,
                         const float* __restrict__ s2, __nv_bfloat16* __restrict__ outb)
{
    size_t i4 = (size_t)blockIdx.x * 256 + threadIdx.x;
    size_t base = i4 * 4;
    int k  = (int)((base >> 12) & 511);
    int bg = (int)(base >> 18);
    float m = mean[bg], r = rstd[bg], w = gnw[k];
    const float invM = 1.0f / (GC * SP);
    float a = s1[bg] * invM, c = s2[bg] * invM;
    uint2 qd = *(const uint2*)(dy16 + base);
    uint2 qh = *(const uint2*)(h1b + base);
    float2 d01 = bf2f(qd.x), d23 = bf2f(qd.y);
    float2 h01 = bf2f(qh.x), h23 = bf2f(qh.y);
    float o0 = r * (w * d01.x - a - (h01.x - m) * r * c);
    float o1 = r * (w * d01.y - a - (h01.y - m) * r * c);
    float o2 = r * (w * d23.x - a - (h23.x - m) * r * c);
    float o3 = r * (w * d23.y - a - (h23.y - m) * r * c);
    __nv_bfloat162 lo = __floats2bfloat162_rn(o0, o1);
    __nv_bfloat162 hi = __floats2bfloat162_rn(o2, o3);
    uint2 pk; pk.x = *(uint32_t*)&lo; pk.y = *(uint32_t*)&hi;
    *(uint2*)(outb + base) = pk;
}

__global__ void reduce_update_k(const float* __restrict__ P, const float* __restrict__ w,
                                float* __restrict__ wf, int MN)
{
    int i = blockIdx.x * 256 + threadIdx.x;
    if (i < MN) {
        float s = 0.f;
        for (int b = 0; b < BN; b++) s += P[(size_t)b * MN + i];
        wf[i] = w[i] - LRf * s;
    }
}

__global__ void gate_k(const float* __restrict__ pools, const float* __restrict__ gw1,
                       const float* __restrict__ gb1, const float* __restrict__ gw2,
                       const float* __restrict__ gb2, float* __restrict__ gate)
{
    const int b = blockIdx.x, j = threadIdx.x;
    float dot = 0.f;
    for (int c = 0; c < CC; c++) dot += pools[b * CC + c] * gw1[j * CC + c];
    float acc = dot * (1.0f / SP) + gb1[j];
    __shared__ float sh[64];
    sh[j] = geluf(acc) * gw2[j];
    __syncthreads();
    for (int o = 32; o > 0; o >>= 1) {
        if (j < o) sh[j] += sh[j + o];
        __syncthreads();
    }
    if (j == 0) gate[b] = 1.0f / (1.0f + expf(-(sh[0] + gb2[0])));
}

#define GSA(v, s) cudaGetSymbolAddress((void**)&v, s)

extern "C" void kernel_launch(void* const* d_in, const int* in_sizes, int n_in,
                              void* d_out, int out_size)
{
    const float* x    = (const float*)d_in[0];
    const int*   mask = (const int*)  d_in[1];
    const float* w1   = (const float*)d_in[2];
    const float* gnw  = (const float*)d_in[3];
    const float* gnb  = (const float*)d_in[4];
    const float* w2   = (const float*)d_in[5];
    const float* rc1  = (const float*)d_in[6];
    const float* rc2  = (const float*)d_in[7];
    const float* gw1  = (const float*)d_in[8];
    const float* gb1  = (const float*)d_in[9];
    const float* gw2  = (const float*)d_in[10];
    const float* gb2  = (const float*)d_in[11];
    const float* rs   = (const float*)d_in[12];
    float* out = (float*)d_out;
    (void)in_sizes; (void)n_in; (void)out_size;

    float *z, *meanb, *rstdb, *cm, *cv, *cnt, *gst, *zst;
    float *Abk, *Bbk, *s1, *s2, *gnwf, *gnbf, *w1f, *w2f, *pw1, *pw2, *pooled, *gate;
    __nv_bfloat16 *h1b, *dy16, *rd16, *pre16, *dp16;
    __nv_bfloat16 *bx, *bxn, *bact, *bactn, *bzm, *bgp, *brd, *bdp, *bdz, *bdzn, *bdyn;
    __nv_bfloat16 *wb1, *wb2, *rb1p, *rb2, *rb2tp, *rb1t, *wb2t, *wb1f, *wb2f;
    GSA(z, g_z); GSA(meanb, g_mean); GSA(rstdb, g_rstd);
    GSA(cm, g_cm); GSA(cv, g_cv); GSA(cnt, g_cnt); GSA(gst, g_gst); GSA(zst, g_zst);
    GSA(Abk, g_Abk); GSA(Bbk, g_Bbk);
    GSA(s1, g_s1); GSA(s2, g_s2); GSA(gnwf, g_gnwf); GSA(gnbf, g_gnbf);
    GSA(w1f, g_w1f); GSA(w2f, g_w2f); GSA(pw1, g_pw1); GSA(pw2, g_pw2);
    GSA(pooled, g_pool); GSA(gate, g_gate);
    GSA(h1b, g_h1b); GSA(dy16, g_dy16); GSA(rd16, g_rd16); GSA(pre16, g_pre16);
    GSA(dp16, g_dp16);
    GSA(bx, g_bx); GSA(bxn, g_bxn); GSA(bact, g_bact); GSA(bactn, g_bactn);
    GSA(bzm, g_bzm); GSA(bgp, g_bgp); GSA(brd, g_brd); GSA(bdp, g_bdp);
    GSA(bdz, g_bdz); GSA(bdzn, g_bdzn); GSA(bdyn, g_bdyn);
    GSA(wb1, g_wb1); GSA(wb2, g_wb2); GSA(rb1p, g_rb1p); GSA(rb2, g_rb2);
    GSA(rb2tp, g_rb2tp); GSA(rb1t, g_rb1t); GSA(wb2t, g_wb2t);
    GSA(wb1f, g_wb1f); GSA(wb2f, g_wb2f);

    // zero accumulators + small independent work
    zero_k<<<32, 256>>>(pooled, BN * CC);
    zero_k<<<2, 256>>>(gst, BN * GRP * 2);
    zero_k<<<2, 256>>>(zst, CC * 2);
    zero_k<<<64, 256>>>(Abk, BN * HID);
    zero_k<<<64, 256>>>(Bbk, BN * HID);
    mask_count_k<<<1, 256>>>(mask, cnt);

    // weight conversions
    wconv_k<<<512, 256>>>(w1,  wb1,  HID, CC, HID, 0, 0);
    wconv_k<<<512, 256>>>(w2,  wb2,  CC, HID, CC, 0, 0);
    wconv_k<<<128, 256>>>(rc1, rb1p, 128, CC, BOT, 0, 0);
    wconv_k<<<64,  256>>>(rc2, rb2,  CC, BOT, CC, 0, 0);
    wconv_k<<<128, 256>>>(rc2, rb2tp, 128, CC, BOT, BOT, 1);
    wconv_k<<<64,  256>>>(rc1, rb1t, CC, BOT, CC, CC, 1);
    wconv_k<<<512, 256>>>(w2,  wb2t, HID, CC, HID, HID, 1);

    // x -> bf16 (T + natural) + fused pooling sums
    tconv_k<CC, 0, true, false, true><<<dim3(64, 4, BN), 256>>>(x, bx, bxn, mask,
        0, 0, 0, 0, pooled);
    gate_k<<<BN, 64>>>(pooled, gw1, gb1, gw2, gb2, gate);

    EpiArgs ez = {};
    // h1 = w1 . x  -> bf16 + fused GN stats
    { EpiArgs ea = ez; ea.gst = gst;
      mmas<EPI_H1, false, true><<<dim3(32, 4, BN), 256>>>(wb1, CC, 0, bx, CC, (size_t)SP * CC,
          (float*)h1b, HID, SP, (size_t)HID * SP, 8, mask, ea); }
    gnfin_k<<<1, BN * GRP>>>(gst, meanb, rstdb);
    // act = gelu(GN(h1)) -> bf16 T + natural
    tconv_k<HID, 3, true, true, false><<<dim3(64, 8, BN), 256>>>(h1b, bact, bactn, mask,
        meanb, rstdb, gnw, gnb, 0);
    // z = w2 . act + x  (+ fused z stats)
    { EpiArgs ea = ez; ea.x = x; ea.zst = zst;
      mmas<EPI_ADDX, false, false><<<dim3(32, 2, BN), 256>>>(wb2, HID, 0, bact, HID,
          (size_t)SP * HID, z, CC, SP, (size_t)CC * SP, 16, mask, ea); }
    zfin_k<<<1, CC>>>(zst, cm, cv);
    // pre = rc1 . (z*mask)  -> bf16
    tconv_k<CC, 1, false, false, false><<<dim3(64, 4, BN), 256>>>(z, bzm, 0, mask,
        0, 0, 0, 0, 0);
    mmas<EPI_STORE, false, true><<<dim3(32, 1, BN), 256>>>(rb1p, CC, 0, bzm, CC,
        (size_t)SP * CC, (float*)pre16, BOT, SP, (size_t)BOT * SP, 8, mask, ez);
    // rdiff = (rc2 . gelu(pre) - z) * inv  -> bf16
    tconv_k<BOT, 2, false, true, false><<<dim3(64, 1, BN), 256>>>(pre16, bgp, 0, mask,
        0, 0, 0, 0, 0);
    { EpiArgs ea = ez; ea.z = z;
      mmas<EPI_RDIFF, false, true><<<dim3(32, 2, BN), 256>>>(rb2, BOT, 0, bgp, BOT,
          (size_t)SP * BOT, (float*)rd16, CC, SP, (size_t)CC * SP, 2, mask, ea); }
    // dpre = (rc2^T . rdiff) * g'(pre) * sc  -> bf16
    tconv_k<CC, 0, false, true, false><<<dim3(64, 4, BN), 256>>>(rd16, brd, 0, mask,
        0, 0, 0, 0, 0);
    { EpiArgs ea = ez; ea.pre16 = pre16; ea.cnt = cnt;
      mmas<EPI_DPRE, false, true><<<dim3(32, 1, BN), 256>>>(rb2tp, CC, 0, brd, CC,
          (size_t)SP * CC, (float*)dp16, BOT, SP, (size_t)BOT * SP, 8, mask, ea); }
    // dz = mask*(rc1^T . dpre) - sc*rdiff + consist  -> bf16 natural directly
    tconv_k<BOT, 0, false, true, false><<<dim3(64, 1, BN), 256>>>(dp16, bdp, 0, mask,
        0, 0, 0, 0, 0);
    { EpiArgs ea = ez; ea.rd16 = rd16; ea.z = z; ea.cm = cm; ea.cv = cv; ea.cnt = cnt;
      mmas<EPI_DZ, false, true><<<dim3(32, 2, BN), 256>>>(rb1t, BOT, 0, bdp, BOT,
          (size_t)SP * BOT, (float*)bdzn, CC, SP, (size_t)CC * SP, 2, mask, ea); }
    // bdz (T layout) from bdzn
    tconv_k<CC, 0, false, true, false><<<dim3(64, 4, BN), 256>>>(bdzn, bdz, 0, mask,
        0, 0, 0, 0, 0);
    // dy = (w2^T . dz) * g'(GN(h1))  -> bf16 + fused bkpart atomics
    { EpiArgs ea = ez; ea.h1b = h1b; ea.mean = meanb; ea.rstd = rstdb;
      ea.gnw = gnw; ea.gnb = gnb; ea.abk = Abk; ea.bbk = Bbk;
      mmas<EPI_DY, false, true><<<dim3(32, 4, BN), 256>>>(wb2t, CC, 0, bdz, CC,
          (size_t)SP * CC, (float*)dy16, HID, SP, (size_t)HID * SP, 8, mask, ea); }
    gn_update_k<<<1, HID>>>(Abk, Bbk, gnw, gnb, gnwf, gnbf);
    s12_k<<<1, BN * GRP>>>(Abk, Bbk, gnw, s1, s2);
    dh1_bf_k<<<65536, 256>>>(dy16, h1b, meanb, rstdb, gnw, s1, s2, bdyn);
    // grad_w1 = dh1 . x^T (split-K over batch, reduce after)
    mmas<EPI_NT, true, false><<<dim3(2, 4, BN), 256>>>(bdyn, SP, (size_t)HID * SP, bxn, SP,
        (size_t)CC * SP, pw1, HID, CC, (size_t)HID * CC, 128, mask, ez);
    reduce_update_k<<<512, 256>>>(pw1, w1, w1f, HID * CC);
    // grad_w2 = dz . act^T
    mmas<EPI_NT, true, false><<<dim3(4, 2, BN), 256>>>(bdzn, SP, (size_t)CC * SP, bactn, SP,
        (size_t)HID * SP, pw2, CC, HID, (size_t)CC * HID, 128, mask, ez);
    reduce_update_k<<<512, 256>>>(pw2, w2, w2f, CC * HID);
    wconv_k<<<512, 256>>>(w1f, wb1f, HID, CC, HID, 0, 0);
    wconv_k<<<512, 256>>>(w2f, wb2f, CC, HID, CC, 0, 0);

    // final modifier at fast weights
    zero_k<<<2, 256>>>(gst, BN * GRP * 2);
    { EpiArgs ea = ez; ea.gst = gst;
      mmas<EPI_H1, false, true><<<dim3(32, 4, BN), 256>>>(wb1f, CC, 0, bx, CC,
          (size_t)SP * CC, (float*)h1b, HID, SP, (size_t)HID * SP, 8, mask, ea); }
    gnfin_k<<<1, BN * GRP>>>(gst, meanb, rstdb);
    tconv_k<HID, 3, false, true, false><<<dim3(64, 8, BN), 256>>>(h1b, bact, 0, mask,
        meanb, rstdb, gnwf, gnbf, 0);
    { EpiArgs ea = ez; ea.x = x; ea.gate = gate; ea.rs = rs;
      mmas<EPI_FINAL, false, false><<<dim3(32, 2, BN), 256>>>(wb2f, HID, 0, bact, HID,
          (size_t)SP * HID, out, CC, SP, (size_t)CC * SP, 16, mask, ea); }
}